// round 9
// baseline (speedup 1.0000x reference)
#include <cuda_runtime.h>
#include <math.h>

#define B 4
#define S 1024
#define F 512
#define H 16
#define D 32
#define M (B*S)

// -------- scratch (no allocations allowed) --------
__device__ float g_qh[B*H*S*D];     // [B,H,S,D]
__device__ float g_kh[B*H*S*D];
__device__ float g_vh[B*H*S*D];
__device__ float g_ctx[B*S*F];      // [B,S,F] context before Wo
__device__ float g_emb2[(2*S+1)*D]; // rel_table @ Wrel

// =======================================================================
// SGEMM: C[M,512] = A[M,512] * W[512,512]
// modes 0/1/2: A = external, write to g_qh/g_kh/g_vh per-head scatter
// mode 3:      A = g_ctx (resolved in DEVICE code!), row-major write to outp
// Tiles: 128(M) x 64(N) x 16(K), 256 threads, 8x4 per-thread register tile
// =======================================================================
#define BM 128
#define BN 64
#define BKT 16

__global__ __launch_bounds__(256) void sgemm_kernel(const float* __restrict__ Ain,
                                                    const float* __restrict__ W,
                                                    float* __restrict__ outp,
                                                    int mode) {
  __shared__ float As[BKT][BM + 4];  // pitch 132 (transposed A tile)
  __shared__ float Ws[BKT][BN + 4];  // pitch 68

  // Device symbols MUST be resolved in device code, never passed from host.
  const float* A = (mode == 3) ? g_ctx : Ain;
  float* out = (mode == 0) ? g_qh : (mode == 1) ? g_kh : (mode == 2) ? g_vh : outp;

  int tid = threadIdx.x;
  int m0 = blockIdx.y * BM;
  int n0 = blockIdx.x * BN;
  int ty = tid >> 4;   // 0..15 -> rows ty*8..+7
  int tx = tid & 15;   // 0..15 -> cols tx*4..+3

  float acc[8][4];
#pragma unroll
  for (int i = 0; i < 8; i++)
#pragma unroll
    for (int j = 0; j < 4; j++) acc[i][j] = 0.f;

  for (int kt0 = 0; kt0 < 512; kt0 += BKT) {
    // load A tile: 128x16 = 512 float4, 2 per thread, stored transposed
#pragma unroll
    for (int u = 0; u < 2; u++) {
      int f = tid + u * 256;
      int r = f >> 2;
      int kk4 = (f & 3) << 2;
      float4 v = *(const float4*)&A[(size_t)(m0 + r) * 512 + kt0 + kk4];
      As[kk4 + 0][r] = v.x;
      As[kk4 + 1][r] = v.y;
      As[kk4 + 2][r] = v.z;
      As[kk4 + 3][r] = v.w;
    }
    // load W tile: 16x64 = 256 float4, 1 per thread
    {
      int kk = tid >> 4;
      int n4 = (tid & 15) << 2;
      *(float4*)&Ws[kk][n4] = *(const float4*)&W[(size_t)(kt0 + kk) * 512 + n0 + n4];
    }
    __syncthreads();

#pragma unroll
    for (int kk = 0; kk < BKT; kk++) {
      float4 a0 = *(const float4*)&As[kk][ty * 8];
      float4 a1 = *(const float4*)&As[kk][ty * 8 + 4];
      float4 w0 = *(const float4*)&Ws[kk][tx * 4];
      float a[8] = {a0.x, a0.y, a0.z, a0.w, a1.x, a1.y, a1.z, a1.w};
      float w[4] = {w0.x, w0.y, w0.z, w0.w};
#pragma unroll
      for (int i = 0; i < 8; i++)
#pragma unroll
        for (int j = 0; j < 4; j++) acc[i][j] += a[i] * w[j];
    }
    __syncthreads();
  }

  int n = n0 + tx * 4;
  if (mode < 3) {
    int hh = n >> 5;   // head
    int dd = n & 31;   // dim within head (multiple of 4 -> float4 ok)
#pragma unroll
    for (int i = 0; i < 8; i++) {
      int mm = m0 + ty * 8 + i;
      int bb = mm >> 10;      // / S
      int ss = mm & 1023;     // % S
      float4 v = make_float4(acc[i][0], acc[i][1], acc[i][2], acc[i][3]);
      *(float4*)&out[(((size_t)(bb * H + hh)) * S + ss) * D + dd] = v;
    }
  } else {
#pragma unroll
    for (int i = 0; i < 8; i++) {
      int mm = m0 + ty * 8 + i;
      float4 v = make_float4(acc[i][0], acc[i][1], acc[i][2], acc[i][3]);
      *(float4*)&out[(size_t)mm * F + n] = v;
    }
  }
}

// =======================================================================
// emb2[t,d] = sum_j rel_table[t,j] * Wrel[j,d]   (2049 x 32)
// =======================================================================
__global__ __launch_bounds__(256) void emb2_kernel(const float* __restrict__ rel,
                                                   const float* __restrict__ Wrel) {
  __shared__ float w[32][33];
  int tid = threadIdx.x;
  for (int i = tid; i < 32 * 32; i += 256) w[i >> 5][i & 31] = Wrel[i];
  __syncthreads();
  int d = tid & 31;
  int tl = tid >> 5;  // 0..7
  int t = blockIdx.x * 8 + tl;
  if (t < 2 * S + 1) {
    float s = 0.f;
#pragma unroll
    for (int j = 0; j < 32; j++) s += rel[t * 32 + j] * w[j][d];
    g_emb2[t * D + d] = s;
  }
}

// =======================================================================
// Fused flash attention with relative-position bias + mask.
// Grid: (S/64, H, B). 256 threads.
// reference dist[q,k] = k - q + S
// =======================================================================
__global__ __launch_bounds__(256) void attn_kernel(const int* __restrict__ mask) {
  __shared__ float qs[64][36];
  __shared__ float ks[64][36];
  __shared__ float vs[64][36];
  __shared__ float reb[127][36];

  int tid = threadIdx.x;
  int qb = blockIdx.x;
  int h = blockIdx.y;
  int b = blockIdx.z;
  int q0 = qb * 64;
  int row = tid >> 2;
  int quarter = tid & 3;

  const float* qbase = g_qh + ((size_t)(b * H + h) * S + q0) * D;
  for (int i = tid; i < 64 * 32; i += 256) {
    int r = i >> 5, c = i & 31;
    qs[r][c] = qbase[i] * 0.17677669529663687f;  // 1/sqrt(D) folded in
  }
  __syncthreads();

  float qreg[32];
#pragma unroll
  for (int j = 0; j < 8; j++) {
    float4 t4 = *(const float4*)&qs[row][4 * j];
    qreg[4 * j + 0] = t4.x;
    qreg[4 * j + 1] = t4.y;
    qreg[4 * j + 2] = t4.z;
    qreg[4 * j + 3] = t4.w;
  }

  float acc[32];
#pragma unroll
  for (int d = 0; d < 32; d++) acc[d] = 0.f;
  float mrun = -INFINITY, l = 0.f;

  const int* mrow = mask + ((size_t)b * S + q0 + row) * S;

  for (int k0 = 0; k0 < S; k0 += 64) {
    __syncthreads();
    const float* kbase = g_kh + ((size_t)(b * H + h) * S + k0) * D;
    const float* vbase = g_vh + ((size_t)(b * H + h) * S + k0) * D;
    for (int i = tid; i < 64 * 32; i += 256) {
      int r = i >> 5, c = i & 31;
      ks[r][c] = kbase[i];
      vs[r][c] = vbase[i];
    }
    // t = (k0+k) - (q0+row) + S = tb + (k - row + 63); tb in [1,1921]
    int tb = k0 - q0 + S - 63;
    for (int i = tid; i < 127 * 32; i += 256) {
      int r = i >> 5, c = i & 31;
      reb[r][c] = g_emb2[(size_t)(tb + r) * D + c];
    }
    __syncthreads();

    float sc[16];
    float tmax = -INFINITY;
#pragma unroll
    for (int i = 0; i < 16; i++) {
      int k = quarter + 4 * i;
      int ridx = k - row + 63;  // in [0,126]
      float s = 0.f;
#pragma unroll
      for (int j = 0; j < 8; j++) {
        float4 k4 = *(const float4*)&ks[k][4 * j];
        float4 e4 = *(const float4*)&reb[ridx][4 * j];
        s += qreg[4 * j + 0] * (k4.x + e4.x);
        s += qreg[4 * j + 1] * (k4.y + e4.y);
        s += qreg[4 * j + 2] * (k4.z + e4.z);
        s += qreg[4 * j + 3] * (k4.w + e4.w);
      }
      if (mrow[k0 + k] <= 0) s = -INFINITY;
      sc[i] = s;
      tmax = fmaxf(tmax, s);
    }
    tmax = fmaxf(tmax, __shfl_xor_sync(0xffffffffu, tmax, 1));
    tmax = fmaxf(tmax, __shfl_xor_sync(0xffffffffu, tmax, 2));
    float mn = fmaxf(mrun, tmax);
    float corr = __expf(mrun - mn);  // first tile: exp(-inf) = 0
    float lsum = 0.f;
#pragma unroll
    for (int i = 0; i < 16; i++) {
      sc[i] = __expf(sc[i] - mn);
      lsum += sc[i];
    }
    lsum += __shfl_xor_sync(0xffffffffu, lsum, 1);
    lsum += __shfl_xor_sync(0xffffffffu, lsum, 2);
    l = l * corr + lsum;
    mrun = mn;
#pragma unroll
    for (int d = 0; d < 32; d++) acc[d] *= corr;

#pragma unroll
    for (int i = 0; i < 16; i++) {
      int k = quarter + 4 * i;
      float pp = sc[i];
#pragma unroll
      for (int j = 0; j < 8; j++) {
        float4 v4 = *(const float4*)&vs[k][4 * j];
        acc[4 * j + 0] += pp * v4.x;
        acc[4 * j + 1] += pp * v4.y;
        acc[4 * j + 2] += pp * v4.z;
        acc[4 * j + 3] += pp * v4.w;
      }
    }
  }

  // reduce partial AV over the 4 quarter-threads of this row
#pragma unroll
  for (int d = 0; d < 32; d++) {
    acc[d] += __shfl_xor_sync(0xffffffffu, acc[d], 1);
    acc[d] += __shfl_xor_sync(0xffffffffu, acc[d], 2);
  }
  float inv = 1.f / l;
  float ov[8];
#pragma unroll
  for (int j = 0; j < 8; j++) {
    float v = (quarter == 0) ? acc[j]
            : (quarter == 1) ? acc[8 + j]
            : (quarter == 2) ? acc[16 + j]
                             : acc[24 + j];
    ov[j] = v * inv;
  }
  float* ob = g_ctx + ((size_t)(b * S + q0 + row)) * F + h * D + quarter * 8;
  *(float4*)&ob[0] = make_float4(ov[0], ov[1], ov[2], ov[3]);
  *(float4*)&ob[4] = make_float4(ov[4], ov[5], ov[6], ov[7]);
}

// =======================================================================
// Host launch: identify inputs by SIZE, not by position.
//   kv,q        : 2,097,152 floats (kv precedes q in both plausible orders)
//   mask        : 4,194,304 int32  (unique)
//   Wq,Wk,Wv,Wo :   262,144 floats (x4; permutation depends on global order)
//   rel_table   :    65,568 floats (unique)
//   Wrel        :     1,024 floats (unique)
// =======================================================================
extern "C" void kernel_launch(void* const* d_in, const int* in_sizes, int n_in,
                              void* d_out, int out_size) {
  const float* big2m[2] = {nullptr, nullptr};
  const float* w512[4]  = {nullptr, nullptr, nullptr, nullptr};
  const int*   mask = nullptr;
  const float* rel = nullptr;
  const float* Wrel = nullptr;
  int nbig = 0, nw = 0;

  for (int i = 0; i < n_in; i++) {
    int sz = in_sizes[i];
    if (sz == B * S * F) {                 // 2,097,152
      if (nbig < 2) big2m[nbig++] = (const float*)d_in[i];
    } else if (sz == B * S * S) {          // 4,194,304
      mask = (const int*)d_in[i];
    } else if (sz == F * F) {              // 262,144
      if (nw < 4) w512[nw++] = (const float*)d_in[i];
    } else if (sz == (2 * S + 1) * D) {    // 65,568
      rel = (const float*)d_in[i];
    } else if (sz == D * D) {              // 1,024
      Wrel = (const float*)d_in[i];
    }
  }

  const float* kv = big2m[0];
  const float* q  = big2m[1];

  const float *Wq, *Wk, *Wv, *Wo;
  if (n_in > 0 && in_sizes[0] == B * S * F) {
    // reference/insertion order: Wq, Wk, Wv, Wo
    Wq = w512[0]; Wk = w512[1]; Wv = w512[2]; Wo = w512[3];
  } else {
    // alphabetical order: Wk, Wo, Wq, Wv
    Wk = w512[0]; Wo = w512[1]; Wq = w512[2]; Wv = w512[3];
  }

  float* out = (float*)d_out;

  dim3 gg(512 / BN, M / BM);  // (8, 32)

  sgemm_kernel<<<gg, 256>>>(q, Wq, nullptr, 0);    // -> g_qh
  sgemm_kernel<<<gg, 256>>>(kv, Wk, nullptr, 1);   // -> g_kh
  sgemm_kernel<<<gg, 256>>>(kv, Wv, nullptr, 2);   // -> g_vh
  emb2_kernel<<<257, 256>>>(rel, Wrel);            // -> g_emb2

  attn_kernel<<<dim3(S / 64, H, B), 256>>>(mask);  // -> g_ctx

  sgemm_kernel<<<gg, 256>>>(nullptr, Wo, out, 3);  // A = g_ctx (device-side) -> d_out
}

// round 11
// speedup vs baseline: 1.0558x; 1.0558x over previous
#include <cuda_runtime.h>
#include <cuda_bf16.h>
#include <cstdint>
#include <math.h>

#define B 4
#define S 1024
#define F 512
#define H 16
#define D 32
#define M (B*S)

// -------- scratch (no allocations allowed) --------
__device__ float g_qh[B*H*S*D];     // [B,H,S,D]
__device__ float g_kh[B*H*S*D];
__device__ float g_vh[B*H*S*D];
__device__ float g_ctx[B*S*F];      // [B,S,F] context before Wo
__device__ float g_emb2[(2*S+1)*D]; // rel_table @ Wrel

// m16n8k16 bf16 MMA, fp32 accum (HMMA path, baseline PTX -> works on compute_103)
#define MMA16816(cc, a, b0v, b1v)                                               \
  asm volatile("mma.sync.aligned.m16n8k16.row.col.f32.bf16.bf16.f32 "           \
               "{%0,%1,%2,%3}, {%4,%5,%6,%7}, {%8,%9}, {%0,%1,%2,%3};"          \
               : "+f"((cc)[0]), "+f"((cc)[1]), "+f"((cc)[2]), "+f"((cc)[3])     \
               : "r"((a)[0]), "r"((a)[1]), "r"((a)[2]), "r"((a)[3]),            \
                 "r"(b0v), "r"(b1v))

// =======================================================================
// Split-bf16 tensor-core GEMM: C[4096,512] = A * W  (passes HH + HL + LH)
// Block 128(M) x 64(N) x 32(K); 8 warps (4M x 2N); warp tile 32x32.
// modes 0/1/2: per-head scatter into g_qh/g_kh/g_vh; mode 3: A=g_ctx -> outp
// =======================================================================
__global__ __launch_bounds__(256) void gemm_mma(const float* __restrict__ Ain,
                                                const float* __restrict__ W,
                                                float* __restrict__ outp,
                                                int mode) {
  __shared__ __nv_bfloat16 Ah[128][40];  // pitch 40 bf16 = 80B -> conflict-free frags
  __shared__ __nv_bfloat16 Al[128][40];
  __shared__ __nv_bfloat16 Bh[64][40];
  __shared__ __nv_bfloat16 Bl[64][40];

  const float* A = (mode == 3) ? g_ctx : Ain;   // device-side symbol resolution
  float* out = (mode == 0) ? g_qh : (mode == 1) ? g_kh : (mode == 2) ? g_vh : outp;

  int tid = threadIdx.x, wid = tid >> 5, lane = tid & 31;
  int wm = wid >> 1, wn = wid & 1;
  int m0 = blockIdx.y * 128, n0 = blockIdx.x * 64;
  int r = lane >> 2, c2 = (lane & 3) * 2;

  float acc[2][4][4];
#pragma unroll
  for (int mt = 0; mt < 2; mt++)
#pragma unroll
    for (int nt = 0; nt < 4; nt++)
#pragma unroll
      for (int i = 0; i < 4; i++) acc[mt][nt][i] = 0.f;

  for (int c = 0; c < 16; c++) {
    int k0 = c * 32;
    // ---- A tile: 128 rows x 32 k, fp32 -> bf16 hi/lo ----
#pragma unroll
    for (int u = 0; u < 2; u++) {
      int f = tid + u * 256;         // 0..511
      int rr = f >> 2;               // 0..127
      int ko = (f & 3) * 8;          // 0,8,16,24
      const float* src = &A[(size_t)(m0 + rr) * 512 + k0 + ko];
      float4 v0 = *(const float4*)&src[0];
      float4 v1 = *(const float4*)&src[4];
      float xs[8] = {v0.x, v0.y, v0.z, v0.w, v1.x, v1.y, v1.z, v1.w};
#pragma unroll
      for (int j = 0; j < 4; j++) {
        __nv_bfloat16 h0 = __float2bfloat16(xs[2 * j]);
        __nv_bfloat16 h1 = __float2bfloat16(xs[2 * j + 1]);
        __nv_bfloat162 ph; ph.x = h0; ph.y = h1;
        __nv_bfloat162 pl;
        pl.x = __float2bfloat16(xs[2 * j] - __bfloat162float(h0));
        pl.y = __float2bfloat16(xs[2 * j + 1] - __bfloat162float(h1));
        *(__nv_bfloat162*)&Ah[rr][ko + 2 * j] = ph;
        *(__nv_bfloat162*)&Al[rr][ko + 2 * j] = pl;
      }
    }
    // ---- B tile: smem[nn][kk] = W[k0+kk][n0+nn] (transpose) ----
#pragma unroll
    for (int u = 0; u < 8; u++) {
      int idx = tid + u * 256;       // 0..2047
      int nn = idx & 63, kk = idx >> 6;
      float x = W[(size_t)(k0 + kk) * 512 + n0 + nn];
      __nv_bfloat16 hh = __float2bfloat16(x);
      Bh[nn][kk] = hh;
      Bl[nn][kk] = __float2bfloat16(x - __bfloat162float(hh));
    }
    __syncthreads();

#pragma unroll
    for (int ks = 0; ks < 2; ks++) {
      int kk = ks * 16;
      uint32_t ah[2][4], al[2][4];
#pragma unroll
      for (int mt = 0; mt < 2; mt++) {
        int rb = wm * 32 + mt * 16;
        ah[mt][0] = *(const uint32_t*)&Ah[rb + r][kk + c2];
        ah[mt][1] = *(const uint32_t*)&Ah[rb + r + 8][kk + c2];
        ah[mt][2] = *(const uint32_t*)&Ah[rb + r][kk + c2 + 8];
        ah[mt][3] = *(const uint32_t*)&Ah[rb + r + 8][kk + c2 + 8];
        al[mt][0] = *(const uint32_t*)&Al[rb + r][kk + c2];
        al[mt][1] = *(const uint32_t*)&Al[rb + r + 8][kk + c2];
        al[mt][2] = *(const uint32_t*)&Al[rb + r][kk + c2 + 8];
        al[mt][3] = *(const uint32_t*)&Al[rb + r + 8][kk + c2 + 8];
      }
      uint32_t bh[4][2], bl[4][2];
#pragma unroll
      for (int nt = 0; nt < 4; nt++) {
        int nb = wn * 32 + nt * 8 + r;
        bh[nt][0] = *(const uint32_t*)&Bh[nb][kk + c2];
        bh[nt][1] = *(const uint32_t*)&Bh[nb][kk + c2 + 8];
        bl[nt][0] = *(const uint32_t*)&Bl[nb][kk + c2];
        bl[nt][1] = *(const uint32_t*)&Bl[nb][kk + c2 + 8];
      }
#pragma unroll
      for (int mt = 0; mt < 2; mt++)
#pragma unroll
        for (int nt = 0; nt < 4; nt++) {
          MMA16816(acc[mt][nt], ah[mt], bh[nt][0], bh[nt][1]);
          MMA16816(acc[mt][nt], ah[mt], bl[nt][0], bl[nt][1]);
          MMA16816(acc[mt][nt], al[mt], bh[nt][0], bh[nt][1]);
        }
    }
    __syncthreads();
  }

  // ---- epilogue ----
#pragma unroll
  for (int mt = 0; mt < 2; mt++)
#pragma unroll
    for (int nt = 0; nt < 4; nt++) {
      int m = m0 + wm * 32 + mt * 16 + r;
      int n = n0 + wn * 32 + nt * 8 + c2;
      if (mode < 3) {
        int hh = n >> 5, dd = n & 31;
        int bb = m >> 10, ss = m & 1023;
        float* o0 = &out[(((size_t)(bb * H + hh)) * S + ss) * D + dd];
        *(float2*)o0 = make_float2(acc[mt][nt][0], acc[mt][nt][1]);
        int m8 = m + 8, bb8 = m8 >> 10, ss8 = m8 & 1023;
        float* o1 = &out[(((size_t)(bb8 * H + hh)) * S + ss8) * D + dd];
        *(float2*)o1 = make_float2(acc[mt][nt][2], acc[mt][nt][3]);
      } else {
        *(float2*)&out[(size_t)m * 512 + n] = make_float2(acc[mt][nt][0], acc[mt][nt][1]);
        *(float2*)&out[(size_t)(m + 8) * 512 + n] = make_float2(acc[mt][nt][2], acc[mt][nt][3]);
      }
    }
}

// =======================================================================
// emb2[t,d] = sum_j rel_table[t,j] * Wrel[j,d]   (2049 x 32)
// =======================================================================
__global__ __launch_bounds__(256) void emb2_kernel(const float* __restrict__ rel,
                                                   const float* __restrict__ Wrel) {
  __shared__ float w[32][33];
  int tid = threadIdx.x;
  for (int i = tid; i < 32 * 32; i += 256) w[i >> 5][i & 31] = Wrel[i];
  __syncthreads();
  int d = tid & 31;
  int tl = tid >> 5;
  int t = blockIdx.x * 8 + tl;
  if (t < 2 * S + 1) {
    float s = 0.f;
#pragma unroll
    for (int j = 0; j < 32; j++) s += rel[t * 32 + j] * w[j][d];
    g_emb2[t * D + d] = s;
  }
}

// =======================================================================
// Fused flash attention with relative-position bias + mask (unchanged, proven).
// Grid: (S/64, H, B). 256 threads. dist[q,k] = k - q + S
// =======================================================================
__global__ __launch_bounds__(256) void attn_kernel(const int* __restrict__ mask) {
  __shared__ float qs[64][36];
  __shared__ float ks[64][36];
  __shared__ float vs[64][36];
  __shared__ float reb[127][36];

  int tid = threadIdx.x;
  int qb = blockIdx.x;
  int h = blockIdx.y;
  int b = blockIdx.z;
  int q0 = qb * 64;
  int row = tid >> 2;
  int quarter = tid & 3;

  const float* qbase = g_qh + ((size_t)(b * H + h) * S + q0) * D;
  for (int i = tid; i < 64 * 32; i += 256) {
    int r = i >> 5, c = i & 31;
    qs[r][c] = qbase[i] * 0.17677669529663687f;
  }
  __syncthreads();

  float qreg[32];
#pragma unroll
  for (int j = 0; j < 8; j++) {
    float4 t4 = *(const float4*)&qs[row][4 * j];
    qreg[4 * j + 0] = t4.x; qreg[4 * j + 1] = t4.y;
    qreg[4 * j + 2] = t4.z; qreg[4 * j + 3] = t4.w;
  }

  float acc[32];
#pragma unroll
  for (int d = 0; d < 32; d++) acc[d] = 0.f;
  float mrun = -INFINITY, l = 0.f;

  const int* mrow = mask + ((size_t)b * S + q0 + row) * S;

  for (int k0 = 0; k0 < S; k0 += 64) {
    __syncthreads();
    const float* kbase = g_kh + ((size_t)(b * H + h) * S + k0) * D;
    const float* vbase = g_vh + ((size_t)(b * H + h) * S + k0) * D;
    for (int i = tid; i < 64 * 32; i += 256) {
      int r = i >> 5, c = i & 31;
      ks[r][c] = kbase[i];
      vs[r][c] = vbase[i];
    }
    int tb = k0 - q0 + S - 63;
    for (int i = tid; i < 127 * 32; i += 256) {
      int r = i >> 5, c = i & 31;
      reb[r][c] = g_emb2[(size_t)(tb + r) * D + c];
    }
    __syncthreads();

    float sc[16];
    float tmax = -INFINITY;
#pragma unroll
    for (int i = 0; i < 16; i++) {
      int k = quarter + 4 * i;
      int ridx = k - row + 63;
      float s = 0.f;
#pragma unroll
      for (int j = 0; j < 8; j++) {
        float4 k4 = *(const float4*)&ks[k][4 * j];
        float4 e4 = *(const float4*)&reb[ridx][4 * j];
        s += qreg[4 * j + 0] * (k4.x + e4.x);
        s += qreg[4 * j + 1] * (k4.y + e4.y);
        s += qreg[4 * j + 2] * (k4.z + e4.z);
        s += qreg[4 * j + 3] * (k4.w + e4.w);
      }
      if (mrow[k0 + k] <= 0) s = -INFINITY;
      sc[i] = s;
      tmax = fmaxf(tmax, s);
    }
    tmax = fmaxf(tmax, __shfl_xor_sync(0xffffffffu, tmax, 1));
    tmax = fmaxf(tmax, __shfl_xor_sync(0xffffffffu, tmax, 2));
    float mn = fmaxf(mrun, tmax);
    float corr = __expf(mrun - mn);
    float lsum = 0.f;
#pragma unroll
    for (int i = 0; i < 16; i++) {
      sc[i] = __expf(sc[i] - mn);
      lsum += sc[i];
    }
    lsum += __shfl_xor_sync(0xffffffffu, lsum, 1);
    lsum += __shfl_xor_sync(0xffffffffu, lsum, 2);
    l = l * corr + lsum;
    mrun = mn;
#pragma unroll
    for (int d = 0; d < 32; d++) acc[d] *= corr;

#pragma unroll
    for (int i = 0; i < 16; i++) {
      int k = quarter + 4 * i;
      float pp = sc[i];
#pragma unroll
      for (int j = 0; j < 8; j++) {
        float4 v4 = *(const float4*)&vs[k][4 * j];
        acc[4 * j + 0] += pp * v4.x;
        acc[4 * j + 1] += pp * v4.y;
        acc[4 * j + 2] += pp * v4.z;
        acc[4 * j + 3] += pp * v4.w;
      }
    }
  }

#pragma unroll
  for (int d = 0; d < 32; d++) {
    acc[d] += __shfl_xor_sync(0xffffffffu, acc[d], 1);
    acc[d] += __shfl_xor_sync(0xffffffffu, acc[d], 2);
  }
  float inv = 1.f / l;
  float ov[8];
#pragma unroll
  for (int j = 0; j < 8; j++) {
    float v = (quarter == 0) ? acc[j]
            : (quarter == 1) ? acc[8 + j]
            : (quarter == 2) ? acc[16 + j]
                             : acc[24 + j];
    ov[j] = v * inv;
  }
  float* ob = g_ctx + ((size_t)(b * S + q0 + row)) * F + h * D + quarter * 8;
  *(float4*)&ob[0] = make_float4(ov[0], ov[1], ov[2], ov[3]);
  *(float4*)&ob[4] = make_float4(ov[4], ov[5], ov[6], ov[7]);
}

// =======================================================================
// Host launch: identify inputs by SIZE (proven working in R9).
// =======================================================================
extern "C" void kernel_launch(void* const* d_in, const int* in_sizes, int n_in,
                              void* d_out, int out_size) {
  const float* big2m[2] = {nullptr, nullptr};
  const float* w512[4]  = {nullptr, nullptr, nullptr, nullptr};
  const int*   mask = nullptr;
  const float* rel = nullptr;
  const float* Wrel = nullptr;
  int nbig = 0, nw = 0;

  for (int i = 0; i < n_in; i++) {
    int sz = in_sizes[i];
    if (sz == B * S * F) {
      if (nbig < 2) big2m[nbig++] = (const float*)d_in[i];
    } else if (sz == B * S * S) {
      mask = (const int*)d_in[i];
    } else if (sz == F * F) {
      if (nw < 4) w512[nw++] = (const float*)d_in[i];
    } else if (sz == (2 * S + 1) * D) {
      rel = (const float*)d_in[i];
    } else if (sz == D * D) {
      Wrel = (const float*)d_in[i];
    }
  }

  const float* kv = big2m[0];
  const float* q  = big2m[1];

  const float *Wq, *Wk, *Wv, *Wo;
  if (n_in > 0 && in_sizes[0] == B * S * F) {
    Wq = w512[0]; Wk = w512[1]; Wv = w512[2]; Wo = w512[3];
  } else {
    Wk = w512[0]; Wo = w512[1]; Wq = w512[2]; Wv = w512[3];
  }

  float* out = (float*)d_out;

  dim3 gg(512 / 64, M / 128);  // (8, 32)

  gemm_mma<<<gg, 256>>>(q, Wq, nullptr, 0);    // -> g_qh
  gemm_mma<<<gg, 256>>>(kv, Wk, nullptr, 1);   // -> g_kh
  gemm_mma<<<gg, 256>>>(kv, Wv, nullptr, 2);   // -> g_vh
  emb2_kernel<<<257, 256>>>(rel, Wrel);        // -> g_emb2

  attn_kernel<<<dim3(S / 64, H, B), 256>>>(mask);  // -> g_ctx

  gemm_mma<<<gg, 256>>>(nullptr, Wo, out, 3);  // A=g_ctx -> d_out
}

// round 12
// speedup vs baseline: 1.0629x; 1.0067x over previous
#include <cuda_runtime.h>
#include <cuda_bf16.h>
#include <cstdint>
#include <math.h>

#define B 4
#define S 1024
#define F 512
#define H 16
#define D 32
#define M (B*S)

// -------- scratch (no allocations allowed) --------
__device__ float g_qh[B*H*S*D];     // [B,H,S,D]
__device__ float g_kh[B*H*S*D];
__device__ float g_vh[B*H*S*D];
__device__ float g_ctx[B*S*F];      // [B,S,F] context before Wo
__device__ float g_emb2[(2*S+1)*D]; // rel_table @ Wrel

// ---------------- packed f32x2 helpers (sm_100+ baseline PTX) ----------------
typedef unsigned long long ull;
#define FMA2(d, a, b, c) \
  asm("fma.rn.f32x2 %0, %1, %2, %3;" : "=l"(d) : "l"(a), "l"(b), "l"(c))
#define ADD2(d, a, b) \
  asm("add.rn.f32x2 %0, %1, %2;" : "=l"(d) : "l"(a), "l"(b))
#define MUL2(d, a, b) \
  asm("mul.rn.f32x2 %0, %1, %2;" : "=l"(d) : "l"(a), "l"(b))
__device__ __forceinline__ ull pk2(float lo, float hi) {
  ull r; asm("mov.b64 %0, {%1,%2};" : "=l"(r) : "f"(lo), "f"(hi)); return r;
}
__device__ __forceinline__ void upk2(ull v, float& lo, float& hi) {
  asm("mov.b64 {%0,%1}, %2;" : "=f"(lo), "=f"(hi) : "l"(v));
}

// m16n8k16 bf16 MMA, fp32 accum (HMMA path, baseline PTX -> works on compute_103)
#define MMA16816(cc, a, b0v, b1v)                                               \
  asm volatile("mma.sync.aligned.m16n8k16.row.col.f32.bf16.bf16.f32 "           \
               "{%0,%1,%2,%3}, {%4,%5,%6,%7}, {%8,%9}, {%0,%1,%2,%3};"          \
               : "+f"((cc)[0]), "+f"((cc)[1]), "+f"((cc)[2]), "+f"((cc)[3])     \
               : "r"((a)[0]), "r"((a)[1]), "r"((a)[2]), "r"((a)[3]),            \
                 "r"(b0v), "r"(b1v))

// =======================================================================
// Split-bf16 tensor-core GEMM (unchanged, proven in R11)
// =======================================================================
__global__ __launch_bounds__(256) void gemm_mma(const float* __restrict__ Ain,
                                                const float* __restrict__ W,
                                                float* __restrict__ outp,
                                                int mode) {
  __shared__ __nv_bfloat16 Ah[128][40];
  __shared__ __nv_bfloat16 Al[128][40];
  __shared__ __nv_bfloat16 Bh[64][40];
  __shared__ __nv_bfloat16 Bl[64][40];

  const float* A = (mode == 3) ? g_ctx : Ain;
  float* out = (mode == 0) ? g_qh : (mode == 1) ? g_kh : (mode == 2) ? g_vh : outp;

  int tid = threadIdx.x, wid = tid >> 5, lane = tid & 31;
  int wm = wid >> 1, wn = wid & 1;
  int m0 = blockIdx.y * 128, n0 = blockIdx.x * 64;
  int r = lane >> 2, c2 = (lane & 3) * 2;

  float acc[2][4][4];
#pragma unroll
  for (int mt = 0; mt < 2; mt++)
#pragma unroll
    for (int nt = 0; nt < 4; nt++)
#pragma unroll
      for (int i = 0; i < 4; i++) acc[mt][nt][i] = 0.f;

  for (int c = 0; c < 16; c++) {
    int k0 = c * 32;
#pragma unroll
    for (int u = 0; u < 2; u++) {
      int f = tid + u * 256;
      int rr = f >> 2;
      int ko = (f & 3) * 8;
      const float* src = &A[(size_t)(m0 + rr) * 512 + k0 + ko];
      float4 v0 = *(const float4*)&src[0];
      float4 v1 = *(const float4*)&src[4];
      float xs[8] = {v0.x, v0.y, v0.z, v0.w, v1.x, v1.y, v1.z, v1.w};
#pragma unroll
      for (int j = 0; j < 4; j++) {
        __nv_bfloat16 h0 = __float2bfloat16(xs[2 * j]);
        __nv_bfloat16 h1 = __float2bfloat16(xs[2 * j + 1]);
        __nv_bfloat162 ph; ph.x = h0; ph.y = h1;
        __nv_bfloat162 pl;
        pl.x = __float2bfloat16(xs[2 * j] - __bfloat162float(h0));
        pl.y = __float2bfloat16(xs[2 * j + 1] - __bfloat162float(h1));
        *(__nv_bfloat162*)&Ah[rr][ko + 2 * j] = ph;
        *(__nv_bfloat162*)&Al[rr][ko + 2 * j] = pl;
      }
    }
#pragma unroll
    for (int u = 0; u < 8; u++) {
      int idx = tid + u * 256;
      int nn = idx & 63, kk = idx >> 6;
      float x = W[(size_t)(k0 + kk) * 512 + n0 + nn];
      __nv_bfloat16 hh = __float2bfloat16(x);
      Bh[nn][kk] = hh;
      Bl[nn][kk] = __float2bfloat16(x - __bfloat162float(hh));
    }
    __syncthreads();

#pragma unroll
    for (int ks = 0; ks < 2; ks++) {
      int kk = ks * 16;
      uint32_t ah[2][4], al[2][4];
#pragma unroll
      for (int mt = 0; mt < 2; mt++) {
        int rb = wm * 32 + mt * 16;
        ah[mt][0] = *(const uint32_t*)&Ah[rb + r][kk + c2];
        ah[mt][1] = *(const uint32_t*)&Ah[rb + r + 8][kk + c2];
        ah[mt][2] = *(const uint32_t*)&Ah[rb + r][kk + c2 + 8];
        ah[mt][3] = *(const uint32_t*)&Ah[rb + r + 8][kk + c2 + 8];
        al[mt][0] = *(const uint32_t*)&Al[rb + r][kk + c2];
        al[mt][1] = *(const uint32_t*)&Al[rb + r + 8][kk + c2];
        al[mt][2] = *(const uint32_t*)&Al[rb + r][kk + c2 + 8];
        al[mt][3] = *(const uint32_t*)&Al[rb + r + 8][kk + c2 + 8];
      }
      uint32_t bh[4][2], bl[4][2];
#pragma unroll
      for (int nt = 0; nt < 4; nt++) {
        int nb = wn * 32 + nt * 8 + r;
        bh[nt][0] = *(const uint32_t*)&Bh[nb][kk + c2];
        bh[nt][1] = *(const uint32_t*)&Bh[nb][kk + c2 + 8];
        bl[nt][0] = *(const uint32_t*)&Bl[nb][kk + c2];
        bl[nt][1] = *(const uint32_t*)&Bl[nb][kk + c2 + 8];
      }
#pragma unroll
      for (int mt = 0; mt < 2; mt++)
#pragma unroll
        for (int nt = 0; nt < 4; nt++) {
          MMA16816(acc[mt][nt], ah[mt], bh[nt][0], bh[nt][1]);
          MMA16816(acc[mt][nt], ah[mt], bl[nt][0], bl[nt][1]);
          MMA16816(acc[mt][nt], al[mt], bh[nt][0], bh[nt][1]);
        }
    }
    __syncthreads();
  }

#pragma unroll
  for (int mt = 0; mt < 2; mt++)
#pragma unroll
    for (int nt = 0; nt < 4; nt++) {
      int m = m0 + wm * 32 + mt * 16 + r;
      int n = n0 + wn * 32 + nt * 8 + c2;
      if (mode < 3) {
        int hh = n >> 5, dd = n & 31;
        int bb = m >> 10, ss = m & 1023;
        float* o0 = &out[(((size_t)(bb * H + hh)) * S + ss) * D + dd];
        *(float2*)o0 = make_float2(acc[mt][nt][0], acc[mt][nt][1]);
        int m8 = m + 8, bb8 = m8 >> 10, ss8 = m8 & 1023;
        float* o1 = &out[(((size_t)(bb8 * H + hh)) * S + ss8) * D + dd];
        *(float2*)o1 = make_float2(acc[mt][nt][2], acc[mt][nt][3]);
      } else {
        *(float2*)&out[(size_t)m * 512 + n] = make_float2(acc[mt][nt][0], acc[mt][nt][1]);
        *(float2*)&out[(size_t)(m + 8) * 512 + n] = make_float2(acc[mt][nt][2], acc[mt][nt][3]);
      }
    }
}

// =======================================================================
// emb2[t,d] = sum_j rel_table[t,j] * Wrel[j,d]   (2049 x 32)
// =======================================================================
__global__ __launch_bounds__(256) void emb2_kernel(const float* __restrict__ rel,
                                                   const float* __restrict__ Wrel) {
  __shared__ float w[32][33];
  int tid = threadIdx.x;
  for (int i = tid; i < 32 * 32; i += 256) w[i >> 5][i & 31] = Wrel[i];
  __syncthreads();
  int d = tid & 31;
  int tl = tid >> 5;
  int t = blockIdx.x * 8 + tl;
  if (t < 2 * S + 1) {
    float s = 0.f;
#pragma unroll
    for (int j = 0; j < 32; j++) s += rel[t * 32 + j] * w[j][d];
    g_emb2[t * D + d] = s;
  }
}

// =======================================================================
// Fused flash attention — packed f32x2 math (halves fma-pipe instructions).
// Grid: (S/64, H, B). 256 threads. dist[q,k] = k - q + S
// =======================================================================
__global__ __launch_bounds__(256) void attn_kernel(const int* __restrict__ mask) {
  __shared__ float qs[64][36];
  __shared__ float ks[64][36];
  __shared__ float vs[64][36];
  __shared__ float reb[127][36];

  int tid = threadIdx.x;
  int qb = blockIdx.x;
  int h = blockIdx.y;
  int b = blockIdx.z;
  int q0 = qb * 64;
  int row = tid >> 2;
  int quarter = tid & 3;

  const float* qbase = g_qh + ((size_t)(b * H + h) * S + q0) * D;
  for (int i = tid; i < 64 * 32; i += 256) {
    int r = i >> 5, c = i & 31;
    qs[r][c] = qbase[i] * 0.17677669529663687f;
  }
  __syncthreads();

  ull qp[16];  // 16 packed f32x2 = 32 q values
#pragma unroll
  for (int j = 0; j < 8; j++) {
    ulonglong2 t2 = *(const ulonglong2*)&qs[row][4 * j];
    qp[2 * j] = t2.x;
    qp[2 * j + 1] = t2.y;
  }

  ull acc2[16];
#pragma unroll
  for (int j = 0; j < 16; j++) acc2[j] = 0ull;
  float mrun = -INFINITY, l = 0.f;

  const int* mrow = mask + ((size_t)b * S + q0 + row) * S;

  for (int k0 = 0; k0 < S; k0 += 64) {
    __syncthreads();
    const float* kbase = g_kh + ((size_t)(b * H + h) * S + k0) * D;
    const float* vbase = g_vh + ((size_t)(b * H + h) * S + k0) * D;
    for (int i = tid; i < 64 * 32; i += 256) {
      int r = i >> 5, c = i & 31;
      ks[r][c] = kbase[i];
      vs[r][c] = vbase[i];
    }
    int tb = k0 - q0 + S - 63;
    for (int i = tid; i < 127 * 32; i += 256) {
      int r = i >> 5, c = i & 31;
      reb[r][c] = g_emb2[(size_t)(tb + r) * D + c];
    }
    __syncthreads();

    float sc[16];
    float tmax = -INFINITY;
#pragma unroll
    for (int i = 0; i < 16; i++) {
      int k = quarter + 4 * i;
      int ridx = k - row + 63;  // in [0,126]
      ull sacc = 0ull;
#pragma unroll
      for (int j = 0; j < 8; j++) {
        ulonglong2 k2 = *(const ulonglong2*)&ks[k][4 * j];
        ulonglong2 e2 = *(const ulonglong2*)&reb[ridx][4 * j];
        ull t0, t1;
        ADD2(t0, k2.x, e2.x);
        FMA2(sacc, qp[2 * j], t0, sacc);
        ADD2(t1, k2.y, e2.y);
        FMA2(sacc, qp[2 * j + 1], t1, sacc);
      }
      float slo, shi;
      upk2(sacc, slo, shi);
      float s = slo + shi;
      if (mrow[k0 + k] <= 0) s = -INFINITY;
      sc[i] = s;
      tmax = fmaxf(tmax, s);
    }
    tmax = fmaxf(tmax, __shfl_xor_sync(0xffffffffu, tmax, 1));
    tmax = fmaxf(tmax, __shfl_xor_sync(0xffffffffu, tmax, 2));
    float mn = fmaxf(mrun, tmax);
    float corr = __expf(mrun - mn);  // first tile: exp(-inf) = 0
    float lsum = 0.f;
#pragma unroll
    for (int i = 0; i < 16; i++) {
      sc[i] = __expf(sc[i] - mn);
      lsum += sc[i];
    }
    lsum += __shfl_xor_sync(0xffffffffu, lsum, 1);
    lsum += __shfl_xor_sync(0xffffffffu, lsum, 2);
    l = l * corr + lsum;
    mrun = mn;
    ull corr2 = pk2(corr, corr);
#pragma unroll
    for (int j = 0; j < 16; j++) MUL2(acc2[j], acc2[j], corr2);

#pragma unroll
    for (int i = 0; i < 16; i++) {
      int k = quarter + 4 * i;
      ull pp2 = pk2(sc[i], sc[i]);
#pragma unroll
      for (int j = 0; j < 8; j++) {
        ulonglong2 v2 = *(const ulonglong2*)&vs[k][4 * j];
        FMA2(acc2[2 * j], pp2, v2.x, acc2[2 * j]);
        FMA2(acc2[2 * j + 1], pp2, v2.y, acc2[2 * j + 1]);
      }
    }
  }

  // unpack + reduce partial AV over the 4 quarter-threads of this row
  float acc[32];
#pragma unroll
  for (int j = 0; j < 16; j++) upk2(acc2[j], acc[2 * j], acc[2 * j + 1]);
#pragma unroll
  for (int d = 0; d < 32; d++) {
    acc[d] += __shfl_xor_sync(0xffffffffu, acc[d], 1);
    acc[d] += __shfl_xor_sync(0xffffffffu, acc[d], 2);
  }
  float inv = 1.f / l;
  float ov[8];
#pragma unroll
  for (int j = 0; j < 8; j++) {
    float v = (quarter == 0) ? acc[j]
            : (quarter == 1) ? acc[8 + j]
            : (quarter == 2) ? acc[16 + j]
                             : acc[24 + j];
    ov[j] = v * inv;
  }
  float* ob = g_ctx + ((size_t)(b * S + q0 + row)) * F + h * D + quarter * 8;
  *(float4*)&ob[0] = make_float4(ov[0], ov[1], ov[2], ov[3]);
  *(float4*)&ob[4] = make_float4(ov[4], ov[5], ov[6], ov[7]);
}

// =======================================================================
// Host launch: identify inputs by SIZE (proven).
// =======================================================================
extern "C" void kernel_launch(void* const* d_in, const int* in_sizes, int n_in,
                              void* d_out, int out_size) {
  const float* big2m[2] = {nullptr, nullptr};
  const float* w512[4]  = {nullptr, nullptr, nullptr, nullptr};
  const int*   mask = nullptr;
  const float* rel = nullptr;
  const float* Wrel = nullptr;
  int nbig = 0, nw = 0;

  for (int i = 0; i < n_in; i++) {
    int sz = in_sizes[i];
    if (sz == B * S * F) {
      if (nbig < 2) big2m[nbig++] = (const float*)d_in[i];
    } else if (sz == B * S * S) {
      mask = (const int*)d_in[i];
    } else if (sz == F * F) {
      if (nw < 4) w512[nw++] = (const float*)d_in[i];
    } else if (sz == (2 * S + 1) * D) {
      rel = (const float*)d_in[i];
    } else if (sz == D * D) {
      Wrel = (const float*)d_in[i];
    }
  }

  const float* kv = big2m[0];
  const float* q  = big2m[1];

  const float *Wq, *Wk, *Wv, *Wo;
  if (n_in > 0 && in_sizes[0] == B * S * F) {
    Wq = w512[0]; Wk = w512[1]; Wv = w512[2]; Wo = w512[3];
  } else {
    Wk = w512[0]; Wo = w512[1]; Wq = w512[2]; Wv = w512[3];
  }

  float* out = (float*)d_out;

  dim3 gg(512 / 64, M / 128);  // (8, 32)

  gemm_mma<<<gg, 256>>>(q, Wq, nullptr, 0);    // -> g_qh
  gemm_mma<<<gg, 256>>>(kv, Wk, nullptr, 1);   // -> g_kh
  gemm_mma<<<gg, 256>>>(kv, Wv, nullptr, 2);   // -> g_vh
  emb2_kernel<<<257, 256>>>(rel, Wrel);        // -> g_emb2

  attn_kernel<<<dim3(S / 64, H, B), 256>>>(mask);  // -> g_ctx

  gemm_mma<<<gg, 256>>>(nullptr, Wo, out, 3);  // A=g_ctx -> d_out
}

// round 13
// speedup vs baseline: 2.1180x; 1.9927x over previous
#include <cuda_runtime.h>
#include <cuda_bf16.h>
#include <cstdint>
#include <math.h>

#define B 4
#define S 1024
#define F 512
#define H 16
#define D 32
#define M (B*S)

// -------- scratch (no allocations allowed) --------
__device__ float g_qh[B*H*S*D];     // [B,H,S,D]
__device__ float g_kh[B*H*S*D];
__device__ float g_vh[B*H*S*D];
__device__ float g_ctx[B*S*F];      // [B,S,F] context before Wo
__device__ float g_emb2[(2*S+1)*D]; // rel_table @ Wrel

// m16n8k16 bf16 MMA, fp32 accum (HMMA, baseline PTX -> compiles for compute_103)
#define MMA16816(cc, a, b0v, b1v)                                               \
  asm volatile("mma.sync.aligned.m16n8k16.row.col.f32.bf16.bf16.f32 "           \
               "{%0,%1,%2,%3}, {%4,%5,%6,%7}, {%8,%9}, {%0,%1,%2,%3};"          \
               : "+f"((cc)[0]), "+f"((cc)[1]), "+f"((cc)[2]), "+f"((cc)[3])     \
               : "r"((a)[0]), "r"((a)[1]), "r"((a)[2]), "r"((a)[3]),            \
                 "r"(b0v), "r"(b1v))

// pack two f32 -> bf16x2 (hi goes to upper 16 bits, lo to lower)
#define CVT2(d, hi, lo) \
  asm("cvt.rn.bf16x2.f32 %0, %1, %2;" : "=r"(d) : "f"(hi), "f"(lo))

// =======================================================================
// Split-bf16 tensor-core GEMM (unchanged, proven since R11)
// =======================================================================
__global__ __launch_bounds__(256) void gemm_mma(const float* __restrict__ Ain,
                                                const float* __restrict__ W,
                                                float* __restrict__ outp,
                                                int mode) {
  __shared__ __nv_bfloat16 Ah[128][40];
  __shared__ __nv_bfloat16 Al[128][40];
  __shared__ __nv_bfloat16 Bh[64][40];
  __shared__ __nv_bfloat16 Bl[64][40];

  const float* A = (mode == 3) ? g_ctx : Ain;
  float* out = (mode == 0) ? g_qh : (mode == 1) ? g_kh : (mode == 2) ? g_vh : outp;

  int tid = threadIdx.x, wid = tid >> 5, lane = tid & 31;
  int wm = wid >> 1, wn = wid & 1;
  int m0 = blockIdx.y * 128, n0 = blockIdx.x * 64;
  int r = lane >> 2, c2 = (lane & 3) * 2;

  float acc[2][4][4];
#pragma unroll
  for (int mt = 0; mt < 2; mt++)
#pragma unroll
    for (int nt = 0; nt < 4; nt++)
#pragma unroll
      for (int i = 0; i < 4; i++) acc[mt][nt][i] = 0.f;

  for (int c = 0; c < 16; c++) {
    int k0 = c * 32;
#pragma unroll
    for (int u = 0; u < 2; u++) {
      int f = tid + u * 256;
      int rr = f >> 2;
      int ko = (f & 3) * 8;
      const float* src = &A[(size_t)(m0 + rr) * 512 + k0 + ko];
      float4 v0 = *(const float4*)&src[0];
      float4 v1 = *(const float4*)&src[4];
      float xs[8] = {v0.x, v0.y, v0.z, v0.w, v1.x, v1.y, v1.z, v1.w};
#pragma unroll
      for (int j = 0; j < 4; j++) {
        __nv_bfloat16 h0 = __float2bfloat16(xs[2 * j]);
        __nv_bfloat16 h1 = __float2bfloat16(xs[2 * j + 1]);
        __nv_bfloat162 ph; ph.x = h0; ph.y = h1;
        __nv_bfloat162 pl;
        pl.x = __float2bfloat16(xs[2 * j] - __bfloat162float(h0));
        pl.y = __float2bfloat16(xs[2 * j + 1] - __bfloat162float(h1));
        *(__nv_bfloat162*)&Ah[rr][ko + 2 * j] = ph;
        *(__nv_bfloat162*)&Al[rr][ko + 2 * j] = pl;
      }
    }
#pragma unroll
    for (int u = 0; u < 8; u++) {
      int idx = tid + u * 256;
      int nn = idx & 63, kk = idx >> 6;
      float x = W[(size_t)(k0 + kk) * 512 + n0 + nn];
      __nv_bfloat16 hh = __float2bfloat16(x);
      Bh[nn][kk] = hh;
      Bl[nn][kk] = __float2bfloat16(x - __bfloat162float(hh));
    }
    __syncthreads();

#pragma unroll
    for (int ks = 0; ks < 2; ks++) {
      int kk = ks * 16;
      uint32_t ah[2][4], al[2][4];
#pragma unroll
      for (int mt = 0; mt < 2; mt++) {
        int rb = wm * 32 + mt * 16;
        ah[mt][0] = *(const uint32_t*)&Ah[rb + r][kk + c2];
        ah[mt][1] = *(const uint32_t*)&Ah[rb + r + 8][kk + c2];
        ah[mt][2] = *(const uint32_t*)&Ah[rb + r][kk + c2 + 8];
        ah[mt][3] = *(const uint32_t*)&Ah[rb + r + 8][kk + c2 + 8];
        al[mt][0] = *(const uint32_t*)&Al[rb + r][kk + c2];
        al[mt][1] = *(const uint32_t*)&Al[rb + r + 8][kk + c2];
        al[mt][2] = *(const uint32_t*)&Al[rb + r][kk + c2 + 8];
        al[mt][3] = *(const uint32_t*)&Al[rb + r + 8][kk + c2 + 8];
      }
      uint32_t bh[4][2], bl[4][2];
#pragma unroll
      for (int nt = 0; nt < 4; nt++) {
        int nb = wn * 32 + nt * 8 + r;
        bh[nt][0] = *(const uint32_t*)&Bh[nb][kk + c2];
        bh[nt][1] = *(const uint32_t*)&Bh[nb][kk + c2 + 8];
        bl[nt][0] = *(const uint32_t*)&Bl[nb][kk + c2];
        bl[nt][1] = *(const uint32_t*)&Bl[nb][kk + c2 + 8];
      }
#pragma unroll
      for (int mt = 0; mt < 2; mt++)
#pragma unroll
        for (int nt = 0; nt < 4; nt++) {
          MMA16816(acc[mt][nt], ah[mt], bh[nt][0], bh[nt][1]);
          MMA16816(acc[mt][nt], ah[mt], bl[nt][0], bl[nt][1]);
          MMA16816(acc[mt][nt], al[mt], bh[nt][0], bh[nt][1]);
        }
    }
    __syncthreads();
  }

#pragma unroll
  for (int mt = 0; mt < 2; mt++)
#pragma unroll
    for (int nt = 0; nt < 4; nt++) {
      int m = m0 + wm * 32 + mt * 16 + r;
      int n = n0 + wn * 32 + nt * 8 + c2;
      if (mode < 3) {
        int hh = n >> 5, dd = n & 31;
        int bb = m >> 10, ss = m & 1023;
        float* o0 = &out[(((size_t)(bb * H + hh)) * S + ss) * D + dd];
        *(float2*)o0 = make_float2(acc[mt][nt][0], acc[mt][nt][1]);
        int m8 = m + 8, bb8 = m8 >> 10, ss8 = m8 & 1023;
        float* o1 = &out[(((size_t)(bb8 * H + hh)) * S + ss8) * D + dd];
        *(float2*)o1 = make_float2(acc[mt][nt][2], acc[mt][nt][3]);
      } else {
        *(float2*)&out[(size_t)m * 512 + n] = make_float2(acc[mt][nt][0], acc[mt][nt][1]);
        *(float2*)&out[(size_t)(m + 8) * 512 + n] = make_float2(acc[mt][nt][2], acc[mt][nt][3]);
      }
    }
}

// =======================================================================
// emb2[t,d] = rel_table @ Wrel   (2049 x 32)
// =======================================================================
__global__ __launch_bounds__(256) void emb2_kernel(const float* __restrict__ rel,
                                                   const float* __restrict__ Wrel) {
  __shared__ float w[32][33];
  int tid = threadIdx.x;
  for (int i = tid; i < 32 * 32; i += 256) w[i >> 5][i & 31] = Wrel[i];
  __syncthreads();
  int d = tid & 31;
  int tl = tid >> 5;
  int t = blockIdx.x * 8 + tl;
  if (t < 2 * S + 1) {
    float s = 0.f;
#pragma unroll
    for (int j = 0; j < 32; j++) s += rel[t * 32 + j] * w[j][d];
    g_emb2[t * D + d] = s;
  }
}

// =======================================================================
// MMA flash attention with fused relative bias.
// Grid (16 qb, 16 h, 4 b), 128 threads = 4 warps, warp owns 16 q-rows.
// Per 64-key tile: one 64x192 score MMA against B=[K(64); emb2_window(127); 0]
//   cols 0..63   = content scores  (3-pass split bf16)
//   cols 64..190 = Qe (bias lookup) (2-pass)
// bias[q,k] = C[q, 64 + (k - q + 63)] via smem; softmax in registers;
// P -> bf16 A-fragments in registers (C-frag == A-frag layout); PV 3-pass.
// =======================================================================
#define AT_QH   0
#define AT_QL   5120
#define AT_KH   10240
#define AT_KL   25600
#define AT_VTH  40960
#define AT_VTL  45568
#define AT_BIAS 50176
#define AT_MSK  84992
#define AT_SMEM 102400

__global__ __launch_bounds__(128) void attn_mma(const int* __restrict__ mask) {
  extern __shared__ char sm[];
  __nv_bfloat16* QH  = (__nv_bfloat16*)(sm + AT_QH);   // [64][40]
  __nv_bfloat16* QL  = (__nv_bfloat16*)(sm + AT_QL);
  __nv_bfloat16* KH  = (__nv_bfloat16*)(sm + AT_KH);   // [192][40]
  __nv_bfloat16* KL  = (__nv_bfloat16*)(sm + AT_KL);
  __nv_bfloat16* VTH = (__nv_bfloat16*)(sm + AT_VTH);  // [32][72] V^T
  __nv_bfloat16* VTL = (__nv_bfloat16*)(sm + AT_VTL);
  float*         BI  = (float*)(sm + AT_BIAS);         // [64][136]
  int*           MS  = (int*)(sm + AT_MSK);            // [64][68]

  int tid = threadIdx.x, wid = tid >> 5, lane = tid & 31;
  int r = lane >> 2, c2 = (lane & 3) * 2;
  int qb = blockIdx.x, h = blockIdx.y, b = blockIdx.z;
  int q0 = qb * 64, wq = wid * 16;
  size_t bh = (size_t)(b * H + h);

  // ---- load Q block (scaled), split bf16 ----
  const float* qsrc = g_qh + (bh * S + q0) * D;
  for (int i = tid; i < 1024; i += 128) {
    int row = i >> 4, cp = (i & 15) * 2;
    float2 v = *(const float2*)&qsrc[row * 32 + cp];
    v.x *= 0.17677669529663687f; v.y *= 0.17677669529663687f;
    __nv_bfloat16 h0 = __float2bfloat16(v.x), h1 = __float2bfloat16(v.y);
    __nv_bfloat162 ph; ph.x = h0; ph.y = h1;
    __nv_bfloat162 pl;
    pl.x = __float2bfloat16(v.x - __bfloat162float(h0));
    pl.y = __float2bfloat16(v.y - __bfloat162float(h1));
    *(__nv_bfloat162*)&QH[row * 40 + cp] = ph;
    *(__nv_bfloat162*)&QL[row * 40 + cp] = pl;
  }
  __syncthreads();

  // ---- Q fragments (persist across k-tiles) ----
  uint32_t aH[2][4], aL[2][4];
#pragma unroll
  for (int ch = 0; ch < 2; ch++) {
    int cb = ch * 16 + c2;
    aH[ch][0] = *(const uint32_t*)&QH[(wq + r) * 40 + cb];
    aH[ch][1] = *(const uint32_t*)&QH[(wq + r + 8) * 40 + cb];
    aH[ch][2] = *(const uint32_t*)&QH[(wq + r) * 40 + cb + 8];
    aH[ch][3] = *(const uint32_t*)&QH[(wq + r + 8) * 40 + cb + 8];
    aL[ch][0] = *(const uint32_t*)&QL[(wq + r) * 40 + cb];
    aL[ch][1] = *(const uint32_t*)&QL[(wq + r + 8) * 40 + cb];
    aL[ch][2] = *(const uint32_t*)&QL[(wq + r) * 40 + cb + 8];
    aL[ch][3] = *(const uint32_t*)&QL[(wq + r + 8) * 40 + cb + 8];
  }

  float O[4][4];
#pragma unroll
  for (int nt = 0; nt < 4; nt++)
#pragma unroll
    for (int i = 0; i < 4; i++) O[nt][i] = 0.f;
  float mo0 = -INFINITY, mo1 = -INFINITY, lo0 = 0.f, lo1 = 0.f;

  for (int k0 = 0; k0 < S; k0 += 64) {
    __syncthreads();  // all warps done with previous tile's smem
    // K tile -> KH/KL rows 0..63
    const float* ksrc = g_kh + (bh * S + k0) * D;
    for (int i = tid; i < 1024; i += 128) {
      int row = i >> 4, cp = (i & 15) * 2;
      float2 v = *(const float2*)&ksrc[row * 32 + cp];
      __nv_bfloat16 h0 = __float2bfloat16(v.x), h1 = __float2bfloat16(v.y);
      __nv_bfloat162 ph; ph.x = h0; ph.y = h1;
      __nv_bfloat162 pl;
      pl.x = __float2bfloat16(v.x - __bfloat162float(h0));
      pl.y = __float2bfloat16(v.y - __bfloat162float(h1));
      *(__nv_bfloat162*)&KH[row * 40 + cp] = ph;
      *(__nv_bfloat162*)&KL[row * 40 + cp] = pl;
    }
    // emb2 window -> rows 64..190; row 191 zero
    int tb = k0 - q0 + S - 63;  // in [1, 1921]
    for (int i = tid; i < 2048; i += 128) {
      int rr = i >> 4, cp = (i & 15) * 2;
      __nv_bfloat162 ph, pl;
      if (rr < 127) {
        float2 v = *(const float2*)&g_emb2[(size_t)(tb + rr) * 32 + cp];
        __nv_bfloat16 h0 = __float2bfloat16(v.x), h1 = __float2bfloat16(v.y);
        ph.x = h0; ph.y = h1;
        pl.x = __float2bfloat16(v.x - __bfloat162float(h0));
        pl.y = __float2bfloat16(v.y - __bfloat162float(h1));
      } else {
        ph.x = __float2bfloat16(0.f); ph.y = ph.x; pl = ph;
      }
      *(__nv_bfloat162*)&KH[(64 + rr) * 40 + cp] = ph;
      *(__nv_bfloat162*)&KL[(64 + rr) * 40 + cp] = pl;
    }
    // V tile transposed -> VTH/VTL [d][kk]
    const float* vsrc = g_vh + (bh * S + k0) * D;
    for (int i = tid; i < 2048; i += 128) {
      int d = i & 31, kk = i >> 5;
      float x = vsrc[kk * 32 + d];
      __nv_bfloat16 hh = __float2bfloat16(x);
      VTH[d * 72 + kk] = hh;
      VTL[d * 72 + kk] = __float2bfloat16(x - __bfloat162float(hh));
    }
    // mask tile
    for (int i = tid; i < 1024; i += 128) {
      int row = i >> 4, c4 = (i & 15) * 4;
      int4 mv = *(const int4*)&mask[((size_t)b * S + q0 + row) * S + k0 + c4];
      *(int4*)&MS[row * 68 + c4] = mv;
    }
    __syncthreads();

    // ---- score MMAs: C[24 tiles][4] ----
    float Cf[24][4];
#pragma unroll
    for (int j = 0; j < 24; j++)
#pragma unroll
      for (int i = 0; i < 4; i++) Cf[j][i] = 0.f;

#pragma unroll
    for (int j = 0; j < 8; j++)    // content: 3-pass
#pragma unroll
      for (int ch = 0; ch < 2; ch++) {
        int ro = (j * 8 + r) * 40 + ch * 16 + c2;
        uint32_t b0h = *(const uint32_t*)&KH[ro];
        uint32_t b1h = *(const uint32_t*)&KH[ro + 8];
        uint32_t b0l = *(const uint32_t*)&KL[ro];
        uint32_t b1l = *(const uint32_t*)&KL[ro + 8];
        MMA16816(Cf[j], aH[ch], b0h, b1h);
        MMA16816(Cf[j], aH[ch], b0l, b1l);
        MMA16816(Cf[j], aL[ch], b0h, b1h);
      }
#pragma unroll
    for (int j = 8; j < 24; j++)   // bias (Qe): 2-pass
#pragma unroll
      for (int ch = 0; ch < 2; ch++) {
        int ro = (j * 8 + r) * 40 + ch * 16 + c2;
        uint32_t b0h = *(const uint32_t*)&KH[ro];
        uint32_t b1h = *(const uint32_t*)&KH[ro + 8];
        uint32_t b0l = *(const uint32_t*)&KL[ro];
        uint32_t b1l = *(const uint32_t*)&KL[ro + 8];
        MMA16816(Cf[j], aH[ch], b0h, b1h);
        MMA16816(Cf[j], aH[ch], b0l, b1l);
      }
    // stash bias tiles (rows belong to this warp only)
#pragma unroll
    for (int j = 8; j < 24; j++) {
      int tl = (j - 8) * 8 + c2;
      *(float2*)&BI[(wq + r) * 136 + tl] = make_float2(Cf[j][0], Cf[j][1]);
      *(float2*)&BI[(wq + r + 8) * 136 + tl] = make_float2(Cf[j][2], Cf[j][3]);
    }
    __syncwarp();

    // ---- softmax (registers + 4-lane shfl) ----
    int qa = wq + r, qbx = qa + 8;
    float tm0 = -INFINITY, tm1 = -INFINITY;
#pragma unroll
    for (int j = 0; j < 8; j++)
#pragma unroll
      for (int e = 0; e < 2; e++) {
        int kk = 8 * j + c2 + e;
        float s0 = Cf[j][e] + BI[qa * 136 + kk - qa + 63];
        if (MS[qa * 68 + kk] <= 0) s0 = -INFINITY;
        Cf[j][e] = s0;
        tm0 = fmaxf(tm0, s0);
        float s1 = Cf[j][2 + e] + BI[qbx * 136 + kk - qbx + 63];
        if (MS[qbx * 68 + kk] <= 0) s1 = -INFINITY;
        Cf[j][2 + e] = s1;
        tm1 = fmaxf(tm1, s1);
      }
    tm0 = fmaxf(tm0, __shfl_xor_sync(0xffffffffu, tm0, 1));
    tm0 = fmaxf(tm0, __shfl_xor_sync(0xffffffffu, tm0, 2));
    tm1 = fmaxf(tm1, __shfl_xor_sync(0xffffffffu, tm1, 1));
    tm1 = fmaxf(tm1, __shfl_xor_sync(0xffffffffu, tm1, 2));
    float mn0 = fmaxf(mo0, tm0), mn1 = fmaxf(mo1, tm1);
    float base0 = (mn0 == -INFINITY) ? 0.f : mn0;
    float base1 = (mn1 == -INFINITY) ? 0.f : mn1;
    float corr0 = (mo0 == -INFINITY) ? 0.f : __expf(mo0 - mn0);
    float corr1 = (mo1 == -INFINITY) ? 0.f : __expf(mo1 - mn1);
    float ls0 = 0.f, ls1 = 0.f;
#pragma unroll
    for (int j = 0; j < 8; j++)
#pragma unroll
      for (int e = 0; e < 2; e++) {
        float p0 = __expf(Cf[j][e] - base0);
        Cf[j][e] = p0; ls0 += p0;
        float p1 = __expf(Cf[j][2 + e] - base1);
        Cf[j][2 + e] = p1; ls1 += p1;
      }
    ls0 += __shfl_xor_sync(0xffffffffu, ls0, 1);
    ls0 += __shfl_xor_sync(0xffffffffu, ls0, 2);
    ls1 += __shfl_xor_sync(0xffffffffu, ls1, 1);
    ls1 += __shfl_xor_sync(0xffffffffu, ls1, 2);
    lo0 = lo0 * corr0 + ls0;
    lo1 = lo1 * corr1 + ls1;
    mo0 = mn0; mo1 = mn1;
#pragma unroll
    for (int nt = 0; nt < 4; nt++) {
      O[nt][0] *= corr0; O[nt][1] *= corr0;
      O[nt][2] *= corr1; O[nt][3] *= corr1;
    }

    // ---- PV: P (registers) @ V^T tiles, 3-pass ----
#pragma unroll
    for (int ch = 0; ch < 4; ch++) {
      uint32_t ph[4], pl[4];
#pragma unroll
      for (int half = 0; half < 2; half++) {   // half 0: rows r / reg 0,1; half 1: rows r+8 / reg 2,3
        float plo = Cf[2 * ch][2 * half + 0], phi = Cf[2 * ch][2 * half + 1];
        uint32_t pk; CVT2(pk, phi, plo);
        ph[half] = pk;
        float rlo = plo - __uint_as_float(pk << 16);
        float rhi = phi - __uint_as_float(pk & 0xffff0000u);
        CVT2(pl[half], rhi, rlo);
        plo = Cf[2 * ch + 1][2 * half + 0]; phi = Cf[2 * ch + 1][2 * half + 1];
        CVT2(pk, phi, plo);
        ph[2 + half] = pk;
        rlo = plo - __uint_as_float(pk << 16);
        rhi = phi - __uint_as_float(pk & 0xffff0000u);
        CVT2(pl[2 + half], rhi, rlo);
      }
      // A-frag order: a0=(r,k lo), a1=(r+8,k lo), a2=(r,k hi), a3=(r+8,k hi)
      uint32_t pA[4] = {ph[0], ph[1], ph[2], ph[3]};
      uint32_t pB[4] = {pl[0], pl[1], pl[2], pl[3]};
#pragma unroll
      for (int nt = 0; nt < 4; nt++) {
        int ro = (nt * 8 + r) * 72 + ch * 16 + c2;
        uint32_t b0h = *(const uint32_t*)&VTH[ro];
        uint32_t b1h = *(const uint32_t*)&VTH[ro + 8];
        uint32_t b0l = *(const uint32_t*)&VTL[ro];
        uint32_t b1l = *(const uint32_t*)&VTL[ro + 8];
        MMA16816(O[nt], pA, b0h, b1h);
        MMA16816(O[nt], pA, b0l, b1l);
        MMA16816(O[nt], pB, b0h, b1h);
      }
    }
  }

  // ---- epilogue ----
  float inv0 = 1.f / lo0, inv1 = 1.f / lo1;
  int qg0 = q0 + wq + r, qg1 = qg0 + 8;
#pragma unroll
  for (int nt = 0; nt < 4; nt++) {
    int col = h * 32 + nt * 8 + c2;
    *(float2*)&g_ctx[((size_t)b * S + qg0) * F + col] =
        make_float2(O[nt][0] * inv0, O[nt][1] * inv0);
    *(float2*)&g_ctx[((size_t)b * S + qg1) * F + col] =
        make_float2(O[nt][2] * inv1, O[nt][3] * inv1);
  }
}

// =======================================================================
// Host launch: identify inputs by SIZE (proven).
// =======================================================================
extern "C" void kernel_launch(void* const* d_in, const int* in_sizes, int n_in,
                              void* d_out, int out_size) {
  const float* big2m[2] = {nullptr, nullptr};
  const float* w512[4]  = {nullptr, nullptr, nullptr, nullptr};
  const int*   mask = nullptr;
  const float* rel = nullptr;
  const float* Wrel = nullptr;
  int nbig = 0, nw = 0;

  for (int i = 0; i < n_in; i++) {
    int sz = in_sizes[i];
    if (sz == B * S * F) {
      if (nbig < 2) big2m[nbig++] = (const float*)d_in[i];
    } else if (sz == B * S * S) {
      mask = (const int*)d_in[i];
    } else if (sz == F * F) {
      if (nw < 4) w512[nw++] = (const float*)d_in[i];
    } else if (sz == (2 * S + 1) * D) {
      rel = (const float*)d_in[i];
    } else if (sz == D * D) {
      Wrel = (const float*)d_in[i];
    }
  }

  const float* kv = big2m[0];
  const float* q  = big2m[1];

  const float *Wq, *Wk, *Wv, *Wo;
  if (n_in > 0 && in_sizes[0] == B * S * F) {
    Wq = w512[0]; Wk = w512[1]; Wv = w512[2]; Wo = w512[3];
  } else {
    Wk = w512[0]; Wo = w512[1]; Wq = w512[2]; Wv = w512[3];
  }

  float* out = (float*)d_out;

  static int smem_set = 0;
  if (!smem_set) {
    cudaFuncSetAttribute(attn_mma, cudaFuncAttributeMaxDynamicSharedMemorySize, AT_SMEM);
    smem_set = 1;
  }

  dim3 gg(512 / 64, M / 128);  // (8, 32)

  gemm_mma<<<gg, 256>>>(q, Wq, nullptr, 0);    // -> g_qh
  gemm_mma<<<gg, 256>>>(kv, Wk, nullptr, 1);   // -> g_kh
  gemm_mma<<<gg, 256>>>(kv, Wv, nullptr, 2);   // -> g_vh
  emb2_kernel<<<257, 256>>>(rel, Wrel);        // -> g_emb2

  attn_mma<<<dim3(16, 16, 4), 128, AT_SMEM>>>(mask);  // -> g_ctx

  gemm_mma<<<gg, 256>>>(nullptr, Wo, out, 3);  // A=g_ctx -> d_out
}

// round 14
// speedup vs baseline: 2.5510x; 1.2044x over previous
#include <cuda_runtime.h>
#include <cuda_bf16.h>
#include <cstdint>
#include <math.h>

#define B 4
#define S 1024
#define F 512
#define H 16
#define D 32
#define M (B*S)

// -------- scratch (no allocations allowed) --------
__device__ __nv_bfloat16 g_qhh[B*H*S*D], g_qhl[B*H*S*D];  // split Q (pre-scaled)
__device__ __nv_bfloat16 g_khh[B*H*S*D], g_khl[B*H*S*D];  // split K
__device__ __nv_bfloat16 g_vhh[B*H*S*D], g_vhl[B*H*S*D];  // split V
__device__ __nv_bfloat16 g_emb2h[(2*S+1)*D], g_emb2l[(2*S+1)*D];
__device__ float g_ctx[B*S*F];                            // context before Wo

// m16n8k16 bf16 MMA, fp32 accum (HMMA, baseline PTX -> compiles for compute_103)
#define MMA16816(cc, a, b0v, b1v)                                               \
  asm volatile("mma.sync.aligned.m16n8k16.row.col.f32.bf16.bf16.f32 "           \
               "{%0,%1,%2,%3}, {%4,%5,%6,%7}, {%8,%9}, {%0,%1,%2,%3};"          \
               : "+f"((cc)[0]), "+f"((cc)[1]), "+f"((cc)[2]), "+f"((cc)[3])     \
               : "r"((a)[0]), "r"((a)[1]), "r"((a)[2]), "r"((a)[3]),            \
                 "r"(b0v), "r"(b1v))

// pack two f32 -> bf16x2 (first arg -> upper 16 bits)
#define CVT2(d, hi, lo) \
  asm("cvt.rn.bf16x2.f32 %0, %1, %2;" : "=r"(d) : "f"(hi), "f"(lo))
// pack two f32 -> f16x2 (first arg -> upper 16 bits)
#define CVTF16X2(d, hi, lo) \
  asm("cvt.rn.f16x2.f32 %0, %1, %2;" : "=r"(d) : "f"(hi), "f"(lo))

__device__ __forceinline__ void st_split(__nv_bfloat16* oh, __nv_bfloat16* ol,
                                         size_t ofs, float a, float b) {
  __nv_bfloat16 h0 = __float2bfloat16(a), h1 = __float2bfloat16(b);
  __nv_bfloat162 ph; ph.x = h0; ph.y = h1;
  __nv_bfloat162 pl;
  pl.x = __float2bfloat16(a - __bfloat162float(h0));
  pl.y = __float2bfloat16(b - __bfloat162float(h1));
  *(__nv_bfloat162*)&oh[ofs] = ph;
  *(__nv_bfloat162*)&ol[ofs] = pl;
}

// =======================================================================
// Split-bf16 tensor-core GEMM. modes 0/1/2: per-head scatter of SPLIT
// bf16 hi/lo into g_{q,k,v}h{h,l} (mode 0 folds 1/sqrt(D) via W scaling).
// mode 3: A=g_ctx (device symbol), fp32 row-major to outp.
// =======================================================================
__global__ __launch_bounds__(256) void gemm_mma(const float* __restrict__ Ain,
                                                const float* __restrict__ W,
                                                float* __restrict__ outp,
                                                int mode) {
  __shared__ __nv_bfloat16 Ah[128][40];
  __shared__ __nv_bfloat16 Al[128][40];
  __shared__ __nv_bfloat16 Bh[64][40];
  __shared__ __nv_bfloat16 Bl[64][40];

  const float* A = (mode == 3) ? g_ctx : Ain;
  float wscale = (mode == 0) ? 0.17677669529663687f : 1.0f;

  int tid = threadIdx.x, wid = tid >> 5, lane = tid & 31;
  int wm = wid >> 1, wn = wid & 1;
  int m0 = blockIdx.y * 128, n0 = blockIdx.x * 64;
  int r = lane >> 2, c2 = (lane & 3) * 2;

  float acc[2][4][4];
#pragma unroll
  for (int mt = 0; mt < 2; mt++)
#pragma unroll
    for (int nt = 0; nt < 4; nt++)
#pragma unroll
      for (int i = 0; i < 4; i++) acc[mt][nt][i] = 0.f;

  for (int c = 0; c < 16; c++) {
    int k0 = c * 32;
#pragma unroll
    for (int u = 0; u < 2; u++) {
      int f = tid + u * 256;
      int rr = f >> 2;
      int ko = (f & 3) * 8;
      const float* src = &A[(size_t)(m0 + rr) * 512 + k0 + ko];
      float4 v0 = *(const float4*)&src[0];
      float4 v1 = *(const float4*)&src[4];
      float xs[8] = {v0.x, v0.y, v0.z, v0.w, v1.x, v1.y, v1.z, v1.w};
#pragma unroll
      for (int j = 0; j < 4; j++) {
        __nv_bfloat16 h0 = __float2bfloat16(xs[2 * j]);
        __nv_bfloat16 h1 = __float2bfloat16(xs[2 * j + 1]);
        __nv_bfloat162 ph; ph.x = h0; ph.y = h1;
        __nv_bfloat162 pl;
        pl.x = __float2bfloat16(xs[2 * j] - __bfloat162float(h0));
        pl.y = __float2bfloat16(xs[2 * j + 1] - __bfloat162float(h1));
        *(__nv_bfloat162*)&Ah[rr][ko + 2 * j] = ph;
        *(__nv_bfloat162*)&Al[rr][ko + 2 * j] = pl;
      }
    }
#pragma unroll
    for (int u = 0; u < 8; u++) {
      int idx = tid + u * 256;
      int nn = idx & 63, kk = idx >> 6;
      float x = W[(size_t)(k0 + kk) * 512 + n0 + nn] * wscale;
      __nv_bfloat16 hh = __float2bfloat16(x);
      Bh[nn][kk] = hh;
      Bl[nn][kk] = __float2bfloat16(x - __bfloat162float(hh));
    }
    __syncthreads();

#pragma unroll
    for (int ks = 0; ks < 2; ks++) {
      int kk = ks * 16;
      uint32_t ah[2][4], al[2][4];
#pragma unroll
      for (int mt = 0; mt < 2; mt++) {
        int rb = wm * 32 + mt * 16;
        ah[mt][0] = *(const uint32_t*)&Ah[rb + r][kk + c2];
        ah[mt][1] = *(const uint32_t*)&Ah[rb + r + 8][kk + c2];
        ah[mt][2] = *(const uint32_t*)&Ah[rb + r][kk + c2 + 8];
        ah[mt][3] = *(const uint32_t*)&Ah[rb + r + 8][kk + c2 + 8];
        al[mt][0] = *(const uint32_t*)&Al[rb + r][kk + c2];
        al[mt][1] = *(const uint32_t*)&Al[rb + r + 8][kk + c2];
        al[mt][2] = *(const uint32_t*)&Al[rb + r][kk + c2 + 8];
        al[mt][3] = *(const uint32_t*)&Al[rb + r + 8][kk + c2 + 8];
      }
      uint32_t bh[4][2], bl[4][2];
#pragma unroll
      for (int nt = 0; nt < 4; nt++) {
        int nb = wn * 32 + nt * 8 + r;
        bh[nt][0] = *(const uint32_t*)&Bh[nb][kk + c2];
        bh[nt][1] = *(const uint32_t*)&Bh[nb][kk + c2 + 8];
        bl[nt][0] = *(const uint32_t*)&Bl[nb][kk + c2];
        bl[nt][1] = *(const uint32_t*)&Bl[nb][kk + c2 + 8];
      }
#pragma unroll
      for (int mt = 0; mt < 2; mt++)
#pragma unroll
        for (int nt = 0; nt < 4; nt++) {
          MMA16816(acc[mt][nt], ah[mt], bh[nt][0], bh[nt][1]);
          MMA16816(acc[mt][nt], ah[mt], bl[nt][0], bl[nt][1]);
          MMA16816(acc[mt][nt], al[mt], bh[nt][0], bh[nt][1]);
        }
    }
    __syncthreads();
  }

  __nv_bfloat16* oh = (mode == 0) ? g_qhh : (mode == 1) ? g_khh : g_vhh;
  __nv_bfloat16* ol = (mode == 0) ? g_qhl : (mode == 1) ? g_khl : g_vhl;
#pragma unroll
  for (int mt = 0; mt < 2; mt++)
#pragma unroll
    for (int nt = 0; nt < 4; nt++) {
      int m = m0 + wm * 32 + mt * 16 + r;
      int n = n0 + wn * 32 + nt * 8 + c2;
      if (mode < 3) {
        int hh = n >> 5, dd = n & 31;
        int bb = m >> 10, ss = m & 1023;
        size_t o0 = (((size_t)(bb * H + hh)) * S + ss) * D + dd;
        st_split(oh, ol, o0, acc[mt][nt][0], acc[mt][nt][1]);
        int m8 = m + 8, bb8 = m8 >> 10, ss8 = m8 & 1023;
        size_t o1 = (((size_t)(bb8 * H + hh)) * S + ss8) * D + dd;
        st_split(oh, ol, o1, acc[mt][nt][2], acc[mt][nt][3]);
      } else {
        *(float2*)&outp[(size_t)m * 512 + n] = make_float2(acc[mt][nt][0], acc[mt][nt][1]);
        *(float2*)&outp[(size_t)(m + 8) * 512 + n] = make_float2(acc[mt][nt][2], acc[mt][nt][3]);
      }
    }
}

// =======================================================================
// emb2 = rel_table @ Wrel (2049 x 32), written as split bf16 hi/lo
// =======================================================================
__global__ __launch_bounds__(256) void emb2_kernel(const float* __restrict__ rel,
                                                   const float* __restrict__ Wrel) {
  __shared__ float w[32][33];
  int tid = threadIdx.x;
  for (int i = tid; i < 32 * 32; i += 256) w[i >> 5][i & 31] = Wrel[i];
  __syncthreads();
  int d = tid & 31;
  int tl = tid >> 5;
  int t = blockIdx.x * 8 + tl;
  if (t < 2 * S + 1) {
    float s = 0.f;
#pragma unroll
    for (int j = 0; j < 32; j++) s += rel[t * 32 + j] * w[j][d];
    __nv_bfloat16 hh = __float2bfloat16(s);
    g_emb2h[t * D + d] = hh;
    g_emb2l[t * D + d] = __float2bfloat16(s - __bfloat162float(hh));
  }
}

// =======================================================================
// MMA flash attention, split operands PRECONVERTED in gmem.
// Grid (16 qb, 16 h, 4 b), 128 threads = 4 warps; warp owns 16 q rows.
// smem 73KB -> 3 CTAs/SM. Tile fills are raw uint4 copies.
// =======================================================================
#define AT_KH   0
#define AT_KL   15360
#define AT_VTH  30720
#define AT_VTL  35328
#define AT_BI   39936
#define AT_MS   57344
#define AT_SMEM 74752

__global__ __launch_bounds__(128, 3) void attn_mma(const int* __restrict__ mask) {
  extern __shared__ char sm[];
  __nv_bfloat16* KH  = (__nv_bfloat16*)(sm + AT_KH);   // [192][40]
  __nv_bfloat16* KL  = (__nv_bfloat16*)(sm + AT_KL);
  __nv_bfloat16* VTH = (__nv_bfloat16*)(sm + AT_VTH);  // [32][72] V^T
  __nv_bfloat16* VTL = (__nv_bfloat16*)(sm + AT_VTL);
  __half*        BI  = (__half*)(sm + AT_BI);          // [64][136]
  int*           MS  = (int*)(sm + AT_MS);             // [64][68]

  int tid = threadIdx.x, wid = tid >> 5, lane = tid & 31;
  int r = lane >> 2, c2 = (lane & 3) * 2;
  int qb = blockIdx.x, h = blockIdx.y, b = blockIdx.z;
  int q0 = qb * 64, wq = wid * 16;
  size_t bh = (size_t)(b * H + h);

  // ---- Q fragments straight from gmem (pre-scaled, pre-split) ----
  uint32_t aH[2][4], aL[2][4];
  {
    size_t rowa = (bh * S + q0 + wq + r) * D;
    size_t rowb = (bh * S + q0 + wq + r + 8) * D;
#pragma unroll
    for (int ch = 0; ch < 2; ch++) {
      int cb = ch * 16 + c2;
      aH[ch][0] = *(const uint32_t*)&g_qhh[rowa + cb];
      aH[ch][1] = *(const uint32_t*)&g_qhh[rowb + cb];
      aH[ch][2] = *(const uint32_t*)&g_qhh[rowa + cb + 8];
      aH[ch][3] = *(const uint32_t*)&g_qhh[rowb + cb + 8];
      aL[ch][0] = *(const uint32_t*)&g_qhl[rowa + cb];
      aL[ch][1] = *(const uint32_t*)&g_qhl[rowb + cb];
      aL[ch][2] = *(const uint32_t*)&g_qhl[rowa + cb + 8];
      aL[ch][3] = *(const uint32_t*)&g_qhl[rowb + cb + 8];
    }
  }

  float O[4][4];
#pragma unroll
  for (int nt = 0; nt < 4; nt++)
#pragma unroll
    for (int i = 0; i < 4; i++) O[nt][i] = 0.f;
  float mo0 = -INFINITY, mo1 = -INFINITY, lo0 = 0.f, lo1 = 0.f;

  for (int k0 = 0; k0 < S; k0 += 64) {
    __syncthreads();
    // K rows 0..63: raw uint4 copies (8 bf16 per uint4)
    for (int i = tid; i < 256; i += 128) {
      int row = i >> 2, c8 = (i & 3) * 8;
      size_t g = (bh * S + k0 + row) * D + c8;
      *(uint4*)&KH[row * 40 + c8] = *(const uint4*)&g_khh[g];
      *(uint4*)&KL[row * 40 + c8] = *(const uint4*)&g_khl[g];
    }
    // emb2 window rows 64..190 (+ zero row 191)
    int tb = k0 - q0 + S - 63;  // in [1, 1921]
    for (int i = tid; i < 512; i += 128) {
      int rr = i >> 2, c8 = (i & 3) * 8;
      uint4 vh = make_uint4(0, 0, 0, 0), vl = make_uint4(0, 0, 0, 0);
      if (rr < 127) {
        size_t g = (size_t)(tb + rr) * D + c8;
        vh = *(const uint4*)&g_emb2h[g];
        vl = *(const uint4*)&g_emb2l[g];
      }
      *(uint4*)&KH[(64 + rr) * 40 + c8] = vh;
      *(uint4*)&KL[(64 + rr) * 40 + c8] = vl;
    }
    // V^T (transpose during fill; no conversion)
    for (int i = tid; i < 1024; i += 128) {
      int kk = i >> 4, d2 = (i & 15) * 2;
      size_t g = (bh * S + k0 + kk) * D + d2;
      __nv_bfloat162 vh = *(const __nv_bfloat162*)&g_vhh[g];
      __nv_bfloat162 vl = *(const __nv_bfloat162*)&g_vhl[g];
      VTH[d2 * 72 + kk] = vh.x; VTH[(d2 + 1) * 72 + kk] = vh.y;
      VTL[d2 * 72 + kk] = vl.x; VTL[(d2 + 1) * 72 + kk] = vl.y;
    }
    // mask tile
    for (int i = tid; i < 1024; i += 128) {
      int row = i >> 4, c4 = (i & 15) * 4;
      int4 mv = *(const int4*)&mask[((size_t)b * S + q0 + row) * S + k0 + c4];
      *(int4*)&MS[row * 68 + c4] = mv;
    }
    __syncthreads();

    // ---- content scores: 8 tiles, 3-pass ----
    float Cf[8][4];
#pragma unroll
    for (int j = 0; j < 8; j++) {
#pragma unroll
      for (int i = 0; i < 4; i++) Cf[j][i] = 0.f;
#pragma unroll
      for (int ch = 0; ch < 2; ch++) {
        int ro = (j * 8 + r) * 40 + ch * 16 + c2;
        uint32_t b0h = *(const uint32_t*)&KH[ro];
        uint32_t b1h = *(const uint32_t*)&KH[ro + 8];
        uint32_t b0l = *(const uint32_t*)&KL[ro];
        uint32_t b1l = *(const uint32_t*)&KL[ro + 8];
        MMA16816(Cf[j], aH[ch], b0h, b1h);
        MMA16816(Cf[j], aH[ch], b0l, b1l);
        MMA16816(Cf[j], aL[ch], b0h, b1h);
      }
    }
    // ---- bias tiles: per-j temp regs, 2-pass, stash to BI (fp16) ----
#pragma unroll
    for (int j = 8; j < 24; j++) {
      float Cb[4] = {0.f, 0.f, 0.f, 0.f};
#pragma unroll
      for (int ch = 0; ch < 2; ch++) {
        int ro = (j * 8 + r) * 40 + ch * 16 + c2;
        uint32_t b0h = *(const uint32_t*)&KH[ro];
        uint32_t b1h = *(const uint32_t*)&KH[ro + 8];
        uint32_t b0l = *(const uint32_t*)&KL[ro];
        uint32_t b1l = *(const uint32_t*)&KL[ro + 8];
        MMA16816(Cb, aH[ch], b0h, b1h);
        MMA16816(Cb, aH[ch], b0l, b1l);
      }
      int tl = (j - 8) * 8 + c2;
      uint32_t p0, p1;
      CVTF16X2(p0, Cb[1], Cb[0]);
      CVTF16X2(p1, Cb[3], Cb[2]);
      *(uint32_t*)&BI[(wq + r) * 136 + tl] = p0;
      *(uint32_t*)&BI[(wq + r + 8) * 136 + tl] = p1;
    }
    __syncwarp();

    // ---- softmax (registers + 4-lane shfl) ----
    int qa = wq + r, qbx = qa + 8;
    float tm0 = -INFINITY, tm1 = -INFINITY;
#pragma unroll
    for (int j = 0; j < 8; j++)
#pragma unroll
      for (int e = 0; e < 2; e++) {
        int kk = 8 * j + c2 + e;
        float s0 = Cf[j][e] + __half2float(BI[qa * 136 + kk - qa + 63]);
        if (MS[qa * 68 + kk] <= 0) s0 = -INFINITY;
        Cf[j][e] = s0;
        tm0 = fmaxf(tm0, s0);
        float s1 = Cf[j][2 + e] + __half2float(BI[qbx * 136 + kk - qbx + 63]);
        if (MS[qbx * 68 + kk] <= 0) s1 = -INFINITY;
        Cf[j][2 + e] = s1;
        tm1 = fmaxf(tm1, s1);
      }
    tm0 = fmaxf(tm0, __shfl_xor_sync(0xffffffffu, tm0, 1));
    tm0 = fmaxf(tm0, __shfl_xor_sync(0xffffffffu, tm0, 2));
    tm1 = fmaxf(tm1, __shfl_xor_sync(0xffffffffu, tm1, 1));
    tm1 = fmaxf(tm1, __shfl_xor_sync(0xffffffffu, tm1, 2));
    float mn0 = fmaxf(mo0, tm0), mn1 = fmaxf(mo1, tm1);
    float base0 = (mn0 == -INFINITY) ? 0.f : mn0;
    float base1 = (mn1 == -INFINITY) ? 0.f : mn1;
    float corr0 = (mo0 == -INFINITY) ? 0.f : __expf(mo0 - mn0);
    float corr1 = (mo1 == -INFINITY) ? 0.f : __expf(mo1 - mn1);
    float ls0 = 0.f, ls1 = 0.f;
#pragma unroll
    for (int j = 0; j < 8; j++)
#pragma unroll
      for (int e = 0; e < 2; e++) {
        float p0 = __expf(Cf[j][e] - base0);
        Cf[j][e] = p0; ls0 += p0;
        float p1 = __expf(Cf[j][2 + e] - base1);
        Cf[j][2 + e] = p1; ls1 += p1;
      }
    ls0 += __shfl_xor_sync(0xffffffffu, ls0, 1);
    ls0 += __shfl_xor_sync(0xffffffffu, ls0, 2);
    ls1 += __shfl_xor_sync(0xffffffffu, ls1, 1);
    ls1 += __shfl_xor_sync(0xffffffffu, ls1, 2);
    lo0 = lo0 * corr0 + ls0;
    lo1 = lo1 * corr1 + ls1;
    mo0 = mn0; mo1 = mn1;
#pragma unroll
    for (int nt = 0; nt < 4; nt++) {
      O[nt][0] *= corr0; O[nt][1] *= corr0;
      O[nt][2] *= corr1; O[nt][3] *= corr1;
    }

    // ---- PV: P (registers, split bf16) @ V^T, 3-pass ----
#pragma unroll
    for (int ch = 0; ch < 4; ch++) {
      uint32_t ph[4], pl[4];
#pragma unroll
      for (int half = 0; half < 2; half++) {
        float plo = Cf[2 * ch][2 * half + 0], phi = Cf[2 * ch][2 * half + 1];
        uint32_t pk; CVT2(pk, phi, plo);
        ph[half] = pk;
        float rlo = plo - __uint_as_float(pk << 16);
        float rhi = phi - __uint_as_float(pk & 0xffff0000u);
        CVT2(pl[half], rhi, rlo);
        plo = Cf[2 * ch + 1][2 * half + 0]; phi = Cf[2 * ch + 1][2 * half + 1];
        CVT2(pk, phi, plo);
        ph[2 + half] = pk;
        rlo = plo - __uint_as_float(pk << 16);
        rhi = phi - __uint_as_float(pk & 0xffff0000u);
        CVT2(pl[2 + half], rhi, rlo);
      }
      uint32_t pA[4] = {ph[0], ph[1], ph[2], ph[3]};
      uint32_t pB[4] = {pl[0], pl[1], pl[2], pl[3]};
#pragma unroll
      for (int nt = 0; nt < 4; nt++) {
        int ro = (nt * 8 + r) * 72 + ch * 16 + c2;
        uint32_t b0h = *(const uint32_t*)&VTH[ro];
        uint32_t b1h = *(const uint32_t*)&VTH[ro + 8];
        uint32_t b0l = *(const uint32_t*)&VTL[ro];
        uint32_t b1l = *(const uint32_t*)&VTL[ro + 8];
        MMA16816(O[nt], pA, b0h, b1h);
        MMA16816(O[nt], pA, b0l, b1l);
        MMA16816(O[nt], pB, b0h, b1h);
      }
    }
  }

  // ---- epilogue ----
  float inv0 = 1.f / lo0, inv1 = 1.f / lo1;
  int qg0 = q0 + wq + r, qg1 = qg0 + 8;
#pragma unroll
  for (int nt = 0; nt < 4; nt++) {
    int col = h * 32 + nt * 8 + c2;
    *(float2*)&g_ctx[((size_t)b * S + qg0) * F + col] =
        make_float2(O[nt][0] * inv0, O[nt][1] * inv0);
    *(float2*)&g_ctx[((size_t)b * S + qg1) * F + col] =
        make_float2(O[nt][2] * inv1, O[nt][3] * inv1);
  }
}

// =======================================================================
// Host launch: identify inputs by SIZE (proven).
// =======================================================================
extern "C" void kernel_launch(void* const* d_in, const int* in_sizes, int n_in,
                              void* d_out, int out_size) {
  const float* big2m[2] = {nullptr, nullptr};
  const float* w512[4]  = {nullptr, nullptr, nullptr, nullptr};
  const int*   mask = nullptr;
  const float* rel = nullptr;
  const float* Wrel = nullptr;
  int nbig = 0, nw = 0;

  for (int i = 0; i < n_in; i++) {
    int sz = in_sizes[i];
    if (sz == B * S * F) {
      if (nbig < 2) big2m[nbig++] = (const float*)d_in[i];
    } else if (sz == B * S * S) {
      mask = (const int*)d_in[i];
    } else if (sz == F * F) {
      if (nw < 4) w512[nw++] = (const float*)d_in[i];
    } else if (sz == (2 * S + 1) * D) {
      rel = (const float*)d_in[i];
    } else if (sz == D * D) {
      Wrel = (const float*)d_in[i];
    }
  }

  const float* kv = big2m[0];
  const float* q  = big2m[1];

  const float *Wq, *Wk, *Wv, *Wo;
  if (n_in > 0 && in_sizes[0] == B * S * F) {
    Wq = w512[0]; Wk = w512[1]; Wv = w512[2]; Wo = w512[3];
  } else {
    Wk = w512[0]; Wo = w512[1]; Wq = w512[2]; Wv = w512[3];
  }

  float* out = (float*)d_out;

  static int smem_set = 0;
  if (!smem_set) {
    cudaFuncSetAttribute(attn_mma, cudaFuncAttributeMaxDynamicSharedMemorySize, AT_SMEM);
    smem_set = 1;
  }

  dim3 gg(512 / 64, M / 128);  // (8, 32)

  gemm_mma<<<gg, 256>>>(q, Wq, nullptr, 0);    // -> split qh (scaled)
  gemm_mma<<<gg, 256>>>(kv, Wk, nullptr, 1);   // -> split kh
  gemm_mma<<<gg, 256>>>(kv, Wv, nullptr, 2);   // -> split vh
  emb2_kernel<<<257, 256>>>(rel, Wrel);        // -> split emb2

  attn_mma<<<dim3(16, 16, 4), 128, AT_SMEM>>>(mask);  // -> g_ctx

  gemm_mma<<<gg, 256>>>(nullptr, Wo, out, 3);  // A=g_ctx -> d_out
}

// round 15
// speedup vs baseline: 2.7339x; 1.0717x over previous
#include <cuda_runtime.h>
#include <cuda_bf16.h>
#include <cstdint>
#include <math.h>

#define B 4
#define S 1024
#define F 512
#define H 16
#define D 32
#define M (B*S)

// -------- scratch (no allocations allowed) --------
__device__ __nv_bfloat16 g_qsh[M*F],  g_qsl[M*F];    // split q input
__device__ __nv_bfloat16 g_kvsh[M*F], g_kvsl[M*F];   // split kv input
__device__ __nv_bfloat16 g_wth[4][F*F], g_wtl[4][F*F]; // split W^T [n][k]; 0=Wq(scaled),1=Wk,2=Wv,3=Wo
__device__ __nv_bfloat16 g_qhh[B*H*S*D], g_qhl[B*H*S*D];
__device__ __nv_bfloat16 g_khh[B*H*S*D], g_khl[B*H*S*D];
__device__ __nv_bfloat16 g_vhh[B*H*S*D], g_vhl[B*H*S*D];
__device__ __nv_bfloat16 g_emb2h[(2*S+1)*D];
__device__ __nv_bfloat16 g_ctxh[B*S*F], g_ctxl[B*S*F];

// m16n8k16 bf16 MMA, fp32 accum (HMMA, baseline PTX)
#define MMA16816(cc, a, b0v, b1v)                                               \
  asm volatile("mma.sync.aligned.m16n8k16.row.col.f32.bf16.bf16.f32 "           \
               "{%0,%1,%2,%3}, {%4,%5,%6,%7}, {%8,%9}, {%0,%1,%2,%3};"          \
               : "+f"((cc)[0]), "+f"((cc)[1]), "+f"((cc)[2]), "+f"((cc)[3])     \
               : "r"((a)[0]), "r"((a)[1]), "r"((a)[2]), "r"((a)[3]),            \
                 "r"(b0v), "r"(b1v))

#define CVT2(d, hi, lo) \
  asm("cvt.rn.bf16x2.f32 %0, %1, %2;" : "=r"(d) : "f"(hi), "f"(lo))
#define CVTF16X2(d, hi, lo) \
  asm("cvt.rn.f16x2.f32 %0, %1, %2;" : "=r"(d) : "f"(hi), "f"(lo))

__device__ __forceinline__ void st_split(__nv_bfloat16* oh, __nv_bfloat16* ol,
                                         size_t ofs, float a, float b) {
  __nv_bfloat16 h0 = __float2bfloat16(a), h1 = __float2bfloat16(b);
  __nv_bfloat162 ph; ph.x = h0; ph.y = h1;
  __nv_bfloat162 pl;
  pl.x = __float2bfloat16(a - __bfloat162float(h0));
  pl.y = __float2bfloat16(b - __bfloat162float(h1));
  *(__nv_bfloat162*)&oh[ofs] = ph;
  *(__nv_bfloat162*)&ol[ofs] = pl;
}

// =======================================================================
// prep: split fp32 inputs into bf16 hi/lo in gmem
// =======================================================================
__global__ __launch_bounds__(256) void split_mat(const float* __restrict__ in,
                                                 int n, int which) {
  __nv_bfloat16* oh = which ? g_kvsh : g_qsh;
  __nv_bfloat16* ol = which ? g_kvsl : g_qsl;
  int j = (blockIdx.x * 256 + threadIdx.x) * 2;
  if (j < n) {
    float2 v = *(const float2*)&in[j];
    st_split(oh, ol, j, v.x, v.y);
  }
}

// W^T split: out[n][k] = w[k][n] * scale
__global__ __launch_bounds__(256) void wtrans(const float* __restrict__ w,
                                              float scale, int which) {
  int j = (blockIdx.x * 256 + threadIdx.x) * 2;   // flat [n][k] index
  int nn = j >> 9, kk = j & 511;
  float a = w[kk * 512 + nn] * scale;
  float b = w[(kk + 1) * 512 + nn] * scale;
  st_split(&g_wth[which][0], &g_wtl[which][0], j, a, b);
}

// =======================================================================
// Copy-fill split-bf16 GEMM. All operands pre-split in gmem.
// modes 0/1/2: A=qs/kvs/kvs, B=wt[mode] -> per-head split scatter.
// mode 3:      A=ctx split,  B=wt[3]    -> fp32 row-major to outp.
// =======================================================================
__global__ __launch_bounds__(256) void gemm_bf16(float* __restrict__ outp, int mode) {
  __shared__ __nv_bfloat16 Ah[128][40];
  __shared__ __nv_bfloat16 Al[128][40];
  __shared__ __nv_bfloat16 Bh[64][40];
  __shared__ __nv_bfloat16 Bl[64][40];

  const __nv_bfloat16* ash = (mode == 0) ? g_qsh : (mode == 3) ? g_ctxh : g_kvsh;
  const __nv_bfloat16* asl = (mode == 0) ? g_qsl : (mode == 3) ? g_ctxl : g_kvsl;
  const __nv_bfloat16* bth = &g_wth[mode][0];
  const __nv_bfloat16* btl = &g_wtl[mode][0];

  int tid = threadIdx.x, wid = tid >> 5, lane = tid & 31;
  int wm = wid >> 1, wn = wid & 1;
  int m0 = blockIdx.y * 128, n0 = blockIdx.x * 64;
  int r = lane >> 2, c2 = (lane & 3) * 2;

  float acc[2][4][4];
#pragma unroll
  for (int mt = 0; mt < 2; mt++)
#pragma unroll
    for (int nt = 0; nt < 4; nt++)
#pragma unroll
      for (int i = 0; i < 4; i++) acc[mt][nt][i] = 0.f;

  for (int c = 0; c < 16; c++) {
    int k0 = c * 32;
    // A tile: 512 uint4 per array, raw copies
#pragma unroll
    for (int u = 0; u < 2; u++) {
      int i = tid + u * 256;
      int rr = i >> 2, c8 = (i & 3) * 8;
      size_t src = (size_t)(m0 + rr) * 512 + k0 + c8;
      *(uint4*)&Ah[rr][c8] = *(const uint4*)&ash[src];
      *(uint4*)&Al[rr][c8] = *(const uint4*)&asl[src];
    }
    // B tile: 256 uint4 per array
    {
      int nn = tid >> 2, c8 = (tid & 3) * 8;
      size_t src = (size_t)(n0 + nn) * 512 + k0 + c8;
      *(uint4*)&Bh[nn][c8] = *(const uint4*)&bth[src];
      *(uint4*)&Bl[nn][c8] = *(const uint4*)&btl[src];
    }
    __syncthreads();

#pragma unroll
    for (int ks = 0; ks < 2; ks++) {
      int kk = ks * 16;
      uint32_t ah[2][4], al[2][4];
#pragma unroll
      for (int mt = 0; mt < 2; mt++) {
        int rb = wm * 32 + mt * 16;
        ah[mt][0] = *(const uint32_t*)&Ah[rb + r][kk + c2];
        ah[mt][1] = *(const uint32_t*)&Ah[rb + r + 8][kk + c2];
        ah[mt][2] = *(const uint32_t*)&Ah[rb + r][kk + c2 + 8];
        ah[mt][3] = *(const uint32_t*)&Ah[rb + r + 8][kk + c2 + 8];
        al[mt][0] = *(const uint32_t*)&Al[rb + r][kk + c2];
        al[mt][1] = *(const uint32_t*)&Al[rb + r + 8][kk + c2];
        al[mt][2] = *(const uint32_t*)&Al[rb + r][kk + c2 + 8];
        al[mt][3] = *(const uint32_t*)&Al[rb + r + 8][kk + c2 + 8];
      }
      uint32_t bh[4][2], bl[4][2];
#pragma unroll
      for (int nt = 0; nt < 4; nt++) {
        int nb = wn * 32 + nt * 8 + r;
        bh[nt][0] = *(const uint32_t*)&Bh[nb][kk + c2];
        bh[nt][1] = *(const uint32_t*)&Bh[nb][kk + c2 + 8];
        bl[nt][0] = *(const uint32_t*)&Bl[nb][kk + c2];
        bl[nt][1] = *(const uint32_t*)&Bl[nb][kk + c2 + 8];
      }
#pragma unroll
      for (int mt = 0; mt < 2; mt++)
#pragma unroll
        for (int nt = 0; nt < 4; nt++) {
          MMA16816(acc[mt][nt], ah[mt], bh[nt][0], bh[nt][1]);
          MMA16816(acc[mt][nt], ah[mt], bl[nt][0], bl[nt][1]);
          MMA16816(acc[mt][nt], al[mt], bh[nt][0], bh[nt][1]);
        }
    }
    __syncthreads();
  }

  __nv_bfloat16* oh = (mode == 0) ? g_qhh : (mode == 1) ? g_khh : g_vhh;
  __nv_bfloat16* ol = (mode == 0) ? g_qhl : (mode == 1) ? g_khl : g_vhl;
#pragma unroll
  for (int mt = 0; mt < 2; mt++)
#pragma unroll
    for (int nt = 0; nt < 4; nt++) {
      int m = m0 + wm * 32 + mt * 16 + r;
      int n = n0 + wn * 32 + nt * 8 + c2;
      if (mode < 3) {
        int hh = n >> 5, dd = n & 31;
        int bb = m >> 10, ss = m & 1023;
        size_t o0 = (((size_t)(bb * H + hh)) * S + ss) * D + dd;
        st_split(oh, ol, o0, acc[mt][nt][0], acc[mt][nt][1]);
        int m8 = m + 8, bb8 = m8 >> 10, ss8 = m8 & 1023;
        size_t o1 = (((size_t)(bb8 * H + hh)) * S + ss8) * D + dd;
        st_split(oh, ol, o1, acc[mt][nt][2], acc[mt][nt][3]);
      } else {
        *(float2*)&outp[(size_t)m * 512 + n] = make_float2(acc[mt][nt][0], acc[mt][nt][1]);
        *(float2*)&outp[(size_t)(m + 8) * 512 + n] = make_float2(acc[mt][nt][2], acc[mt][nt][3]);
      }
    }
}

// =======================================================================
// emb2 = rel_table @ Wrel (2049 x 32), bf16 hi only (bias is 1-pass)
// =======================================================================
__global__ __launch_bounds__(256) void emb2_kernel(const float* __restrict__ rel,
                                                   const float* __restrict__ Wrel) {
  __shared__ float w[32][33];
  int tid = threadIdx.x;
  for (int i = tid; i < 32 * 32; i += 256) w[i >> 5][i & 31] = Wrel[i];
  __syncthreads();
  int d = tid & 31;
  int tl = tid >> 5;
  int t = blockIdx.x * 8 + tl;
  if (t < 2 * S + 1) {
    float s = 0.f;
#pragma unroll
    for (int j = 0; j < 32; j++) s += rel[t * 32 + j] * w[j][d];
    g_emb2h[t * D + d] = __float2bfloat16(s);
  }
}

// =======================================================================
// MMA flash attention. 1-pass bias; split ctx output; 64.5KB smem.
// Grid (16 qb, 16 h, 4 b), 128 threads = 4 warps; warp owns 16 q rows.
// =======================================================================
#define AT_KH   0
#define AT_KL   15360
#define AT_VTH  20480
#define AT_VTL  25088
#define AT_BI   29696
#define AT_MS   47104
#define AT_SMEM 64512

__global__ __launch_bounds__(128, 3) void attn_mma(const int* __restrict__ mask) {
  extern __shared__ char sm[];
  __nv_bfloat16* KH  = (__nv_bfloat16*)(sm + AT_KH);   // [192][40] (64 K rows + 127 emb2 + pad)
  __nv_bfloat16* KL  = (__nv_bfloat16*)(sm + AT_KL);   // [64][40]  (K low only)
  __nv_bfloat16* VTH = (__nv_bfloat16*)(sm + AT_VTH);  // [32][72]
  __nv_bfloat16* VTL = (__nv_bfloat16*)(sm + AT_VTL);
  __half*        BI  = (__half*)(sm + AT_BI);          // [64][136]
  int*           MS  = (int*)(sm + AT_MS);             // [64][68]

  int tid = threadIdx.x, wid = tid >> 5, lane = tid & 31;
  int r = lane >> 2, c2 = (lane & 3) * 2;
  int qb = blockIdx.x, h = blockIdx.y, b = blockIdx.z;
  int q0 = qb * 64, wq = wid * 16;
  size_t bh = (size_t)(b * H + h);

  // Q fragments from gmem (pre-scaled, pre-split)
  uint32_t aH[2][4], aL[2][4];
  {
    size_t rowa = (bh * S + q0 + wq + r) * D;
    size_t rowb = (bh * S + q0 + wq + r + 8) * D;
#pragma unroll
    for (int ch = 0; ch < 2; ch++) {
      int cb = ch * 16 + c2;
      aH[ch][0] = *(const uint32_t*)&g_qhh[rowa + cb];
      aH[ch][1] = *(const uint32_t*)&g_qhh[rowb + cb];
      aH[ch][2] = *(const uint32_t*)&g_qhh[rowa + cb + 8];
      aH[ch][3] = *(const uint32_t*)&g_qhh[rowb + cb + 8];
      aL[ch][0] = *(const uint32_t*)&g_qhl[rowa + cb];
      aL[ch][1] = *(const uint32_t*)&g_qhl[rowb + cb];
      aL[ch][2] = *(const uint32_t*)&g_qhl[rowa + cb + 8];
      aL[ch][3] = *(const uint32_t*)&g_qhl[rowb + cb + 8];
    }
  }

  float O[4][4];
#pragma unroll
  for (int nt = 0; nt < 4; nt++)
#pragma unroll
    for (int i = 0; i < 4; i++) O[nt][i] = 0.f;
  float mo0 = -INFINITY, mo1 = -INFINITY, lo0 = 0.f, lo1 = 0.f;

  for (int k0 = 0; k0 < S; k0 += 64) {
    __syncthreads();
    // K rows 0..63 (hi+lo)
    for (int i = tid; i < 256; i += 128) {
      int row = i >> 2, c8 = (i & 3) * 8;
      size_t g = (bh * S + k0 + row) * D + c8;
      *(uint4*)&KH[row * 40 + c8] = *(const uint4*)&g_khh[g];
      *(uint4*)&KL[row * 40 + c8] = *(const uint4*)&g_khl[g];
    }
    // emb2 window rows 64..190 (hi only; row 191 zero)
    int tb = k0 - q0 + S - 63;  // in [1, 1921]
    for (int i = tid; i < 512; i += 128) {
      int rr = i >> 2, c8 = (i & 3) * 8;
      uint4 vh = make_uint4(0, 0, 0, 0);
      if (rr < 127) vh = *(const uint4*)&g_emb2h[(size_t)(tb + rr) * D + c8];
      *(uint4*)&KH[(64 + rr) * 40 + c8] = vh;
    }
    // V^T
    for (int i = tid; i < 1024; i += 128) {
      int kk = i >> 4, d2 = (i & 15) * 2;
      size_t g = (bh * S + k0 + kk) * D + d2;
      __nv_bfloat162 vh = *(const __nv_bfloat162*)&g_vhh[g];
      __nv_bfloat162 vl = *(const __nv_bfloat162*)&g_vhl[g];
      VTH[d2 * 72 + kk] = vh.x; VTH[(d2 + 1) * 72 + kk] = vh.y;
      VTL[d2 * 72 + kk] = vl.x; VTL[(d2 + 1) * 72 + kk] = vl.y;
    }
    // mask tile
    for (int i = tid; i < 1024; i += 128) {
      int row = i >> 4, c4 = (i & 15) * 4;
      int4 mv = *(const int4*)&mask[((size_t)b * S + q0 + row) * S + k0 + c4];
      *(int4*)&MS[row * 68 + c4] = mv;
    }
    __syncthreads();

    // content scores: 8 tiles, 3-pass
    float Cf[8][4];
#pragma unroll
    for (int j = 0; j < 8; j++) {
#pragma unroll
      for (int i = 0; i < 4; i++) Cf[j][i] = 0.f;
#pragma unroll
      for (int ch = 0; ch < 2; ch++) {
        int ro = (j * 8 + r) * 40 + ch * 16 + c2;
        uint32_t b0h = *(const uint32_t*)&KH[ro];
        uint32_t b1h = *(const uint32_t*)&KH[ro + 8];
        uint32_t b0l = *(const uint32_t*)&KL[ro];
        uint32_t b1l = *(const uint32_t*)&KL[ro + 8];
        MMA16816(Cf[j], aH[ch], b0h, b1h);
        MMA16816(Cf[j], aH[ch], b0l, b1l);
        MMA16816(Cf[j], aL[ch], b0h, b1h);
      }
    }
    // bias tiles: 1-pass (Qh x emb2h), stash fp16
#pragma unroll
    for (int j = 8; j < 24; j++) {
      float Cb[4] = {0.f, 0.f, 0.f, 0.f};
#pragma unroll
      for (int ch = 0; ch < 2; ch++) {
        int ro = (j * 8 + r) * 40 + ch * 16 + c2;
        uint32_t b0h = *(const uint32_t*)&KH[ro];
        uint32_t b1h = *(const uint32_t*)&KH[ro + 8];
        MMA16816(Cb, aH[ch], b0h, b1h);
      }
      int tl = (j - 8) * 8 + c2;
      uint32_t p0, p1;
      CVTF16X2(p0, Cb[1], Cb[0]);
      CVTF16X2(p1, Cb[3], Cb[2]);
      *(uint32_t*)&BI[(wq + r) * 136 + tl] = p0;
      *(uint32_t*)&BI[(wq + r + 8) * 136 + tl] = p1;
    }
    __syncwarp();

    // softmax
    int qa = wq + r, qbx = qa + 8;
    float tm0 = -INFINITY, tm1 = -INFINITY;
#pragma unroll
    for (int j = 0; j < 8; j++)
#pragma unroll
      for (int e = 0; e < 2; e++) {
        int kk = 8 * j + c2 + e;
        float s0 = Cf[j][e] + __half2float(BI[qa * 136 + kk - qa + 63]);
        if (MS[qa * 68 + kk] <= 0) s0 = -INFINITY;
        Cf[j][e] = s0;
        tm0 = fmaxf(tm0, s0);
        float s1 = Cf[j][2 + e] + __half2float(BI[qbx * 136 + kk - qbx + 63]);
        if (MS[qbx * 68 + kk] <= 0) s1 = -INFINITY;
        Cf[j][2 + e] = s1;
        tm1 = fmaxf(tm1, s1);
      }
    tm0 = fmaxf(tm0, __shfl_xor_sync(0xffffffffu, tm0, 1));
    tm0 = fmaxf(tm0, __shfl_xor_sync(0xffffffffu, tm0, 2));
    tm1 = fmaxf(tm1, __shfl_xor_sync(0xffffffffu, tm1, 1));
    tm1 = fmaxf(tm1, __shfl_xor_sync(0xffffffffu, tm1, 2));
    float mn0 = fmaxf(mo0, tm0), mn1 = fmaxf(mo1, tm1);
    float base0 = (mn0 == -INFINITY) ? 0.f : mn0;
    float base1 = (mn1 == -INFINITY) ? 0.f : mn1;
    float corr0 = (mo0 == -INFINITY) ? 0.f : __expf(mo0 - mn0);
    float corr1 = (mo1 == -INFINITY) ? 0.f : __expf(mo1 - mn1);
    float ls0 = 0.f, ls1 = 0.f;
#pragma unroll
    for (int j = 0; j < 8; j++)
#pragma unroll
      for (int e = 0; e < 2; e++) {
        float p0 = __expf(Cf[j][e] - base0);
        Cf[j][e] = p0; ls0 += p0;
        float p1 = __expf(Cf[j][2 + e] - base1);
        Cf[j][2 + e] = p1; ls1 += p1;
      }
    ls0 += __shfl_xor_sync(0xffffffffu, ls0, 1);
    ls0 += __shfl_xor_sync(0xffffffffu, ls0, 2);
    ls1 += __shfl_xor_sync(0xffffffffu, ls1, 1);
    ls1 += __shfl_xor_sync(0xffffffffu, ls1, 2);
    lo0 = lo0 * corr0 + ls0;
    lo1 = lo1 * corr1 + ls1;
    mo0 = mn0; mo1 = mn1;
#pragma unroll
    for (int nt = 0; nt < 4; nt++) {
      O[nt][0] *= corr0; O[nt][1] *= corr0;
      O[nt][2] *= corr1; O[nt][3] *= corr1;
    }

    // PV: split P @ V^T, 3-pass
#pragma unroll
    for (int ch = 0; ch < 4; ch++) {
      uint32_t ph[4], pl[4];
#pragma unroll
      for (int half = 0; half < 2; half++) {
        float plo = Cf[2 * ch][2 * half + 0], phi = Cf[2 * ch][2 * half + 1];
        uint32_t pk; CVT2(pk, phi, plo);
        ph[half] = pk;
        float rlo = plo - __uint_as_float(pk << 16);
        float rhi = phi - __uint_as_float(pk & 0xffff0000u);
        CVT2(pl[half], rhi, rlo);
        plo = Cf[2 * ch + 1][2 * half + 0]; phi = Cf[2 * ch + 1][2 * half + 1];
        CVT2(pk, phi, plo);
        ph[2 + half] = pk;
        rlo = plo - __uint_as_float(pk << 16);
        rhi = phi - __uint_as_float(pk & 0xffff0000u);
        CVT2(pl[2 + half], rhi, rlo);
      }
      uint32_t pA[4] = {ph[0], ph[1], ph[2], ph[3]};
      uint32_t pB[4] = {pl[0], pl[1], pl[2], pl[3]};
#pragma unroll
      for (int nt = 0; nt < 4; nt++) {
        int ro = (nt * 8 + r) * 72 + ch * 16 + c2;
        uint32_t b0h = *(const uint32_t*)&VTH[ro];
        uint32_t b1h = *(const uint32_t*)&VTH[ro + 8];
        uint32_t b0l = *(const uint32_t*)&VTL[ro];
        uint32_t b1l = *(const uint32_t*)&VTL[ro + 8];
        MMA16816(O[nt], pA, b0h, b1h);
        MMA16816(O[nt], pA, b0l, b1l);
        MMA16816(O[nt], pB, b0h, b1h);
      }
    }
  }

  // epilogue -> split ctx
  float inv0 = 1.f / lo0, inv1 = 1.f / lo1;
  int qg0 = q0 + wq + r, qg1 = qg0 + 8;
#pragma unroll
  for (int nt = 0; nt < 4; nt++) {
    int col = h * 32 + nt * 8 + c2;
    st_split(g_ctxh, g_ctxl, ((size_t)b * S + qg0) * F + col,
             O[nt][0] * inv0, O[nt][1] * inv0);
    st_split(g_ctxh, g_ctxl, ((size_t)b * S + qg1) * F + col,
             O[nt][2] * inv1, O[nt][3] * inv1);
  }
}

// =======================================================================
// Host launch: identify inputs by SIZE (proven).
// =======================================================================
extern "C" void kernel_launch(void* const* d_in, const int* in_sizes, int n_in,
                              void* d_out, int out_size) {
  const float* big2m[2] = {nullptr, nullptr};
  const float* w512[4]  = {nullptr, nullptr, nullptr, nullptr};
  const int*   mask = nullptr;
  const float* rel = nullptr;
  const float* Wrel = nullptr;
  int nbig = 0, nw = 0;

  for (int i = 0; i < n_in; i++) {
    int sz = in_sizes[i];
    if (sz == B * S * F) {
      if (nbig < 2) big2m[nbig++] = (const float*)d_in[i];
    } else if (sz == B * S * S) {
      mask = (const int*)d_in[i];
    } else if (sz == F * F) {
      if (nw < 4) w512[nw++] = (const float*)d_in[i];
    } else if (sz == (2 * S + 1) * D) {
      rel = (const float*)d_in[i];
    } else if (sz == D * D) {
      Wrel = (const float*)d_in[i];
    }
  }

  const float* kv = big2m[0];
  const float* q  = big2m[1];

  const float *Wq, *Wk, *Wv, *Wo;
  if (n_in > 0 && in_sizes[0] == B * S * F) {
    Wq = w512[0]; Wk = w512[1]; Wv = w512[2]; Wo = w512[3];
  } else {
    Wk = w512[0]; Wo = w512[1]; Wq = w512[2]; Wv = w512[3];
  }

  float* out = (float*)d_out;

  static int smem_set = 0;
  if (!smem_set) {
    cudaFuncSetAttribute(attn_mma, cudaFuncAttributeMaxDynamicSharedMemorySize, AT_SMEM);
    smem_set = 1;
  }

  // prep: split inputs + transposed split weights
  split_mat<<<4096, 256>>>(q, M * F, 0);
  split_mat<<<4096, 256>>>(kv, M * F, 1);
  wtrans<<<512, 256>>>(Wq, 0.17677669529663687f, 0);
  wtrans<<<512, 256>>>(Wk, 1.0f, 1);
  wtrans<<<512, 256>>>(Wv, 1.0f, 2);
  wtrans<<<512, 256>>>(Wo, 1.0f, 3);
  emb2_kernel<<<257, 256>>>(rel, Wrel);

  dim3 gg(512 / 64, M / 128);  // (8, 32)
  gemm_bf16<<<gg, 256>>>(nullptr, 0);  // -> split qh (scaled)
  gemm_bf16<<<gg, 256>>>(nullptr, 1);  // -> split kh
  gemm_bf16<<<gg, 256>>>(nullptr, 2);  // -> split vh

  attn_mma<<<dim3(16, 16, 4), 128, AT_SMEM>>>(mask);  // -> split ctx

  gemm_bf16<<<gg, 256>>>(out, 3);      // ctx @ Wo -> d_out
}

// round 16
// speedup vs baseline: 3.2462x; 1.1874x over previous
#include <cuda_runtime.h>
#include <cuda_bf16.h>
#include <cstdint>
#include <math.h>

#define B 4
#define S 1024
#define F 512
#define H 16
#define D 32
#define M (B*S)

// -------- scratch (no allocations allowed) --------
__device__ __nv_bfloat16 g_qsh[M*F],  g_qsl[M*F];      // split q input
__device__ __nv_bfloat16 g_kvsh[M*F], g_kvsl[M*F];     // split kv input
__device__ __nv_bfloat16 g_wth[4][F*F], g_wtl[4][F*F]; // split W^T [n][k]
__device__ __nv_bfloat16 g_qhh[B*H*S*D], g_qhl[B*H*S*D];
__device__ __nv_bfloat16 g_khh[B*H*S*D], g_khl[B*H*S*D];
__device__ __nv_bfloat16 g_vth[B*H*D*S], g_vtl[B*H*D*S]; // V TRANSPOSED [b,h,d,s]
__device__ __nv_bfloat16 g_emb2h[(2*S+1)*D];
__device__ __nv_bfloat16 g_ctxh[B*S*F], g_ctxl[B*S*F];
__device__ uint32_t g_mbits[B*S*S/32];                 // packed mask bits

// m16n8k16 bf16 MMA, fp32 accum (HMMA, baseline PTX)
#define MMA16816(cc, a, b0v, b1v)                                               \
  asm volatile("mma.sync.aligned.m16n8k16.row.col.f32.bf16.bf16.f32 "           \
               "{%0,%1,%2,%3}, {%4,%5,%6,%7}, {%8,%9}, {%0,%1,%2,%3};"          \
               : "+f"((cc)[0]), "+f"((cc)[1]), "+f"((cc)[2]), "+f"((cc)[3])     \
               : "r"((a)[0]), "r"((a)[1]), "r"((a)[2]), "r"((a)[3]),            \
                 "r"(b0v), "r"(b1v))

#define CVT2(d, hi, lo) \
  asm("cvt.rn.bf16x2.f32 %0, %1, %2;" : "=r"(d) : "f"(hi), "f"(lo))
#define CVTF16X2(d, hi, lo) \
  asm("cvt.rn.f16x2.f32 %0, %1, %2;" : "=r"(d) : "f"(hi), "f"(lo))

__device__ __forceinline__ void st_split(__nv_bfloat16* oh, __nv_bfloat16* ol,
                                         size_t ofs, float a, float b) {
  __nv_bfloat16 h0 = __float2bfloat16(a), h1 = __float2bfloat16(b);
  __nv_bfloat162 ph; ph.x = h0; ph.y = h1;
  __nv_bfloat162 pl;
  pl.x = __float2bfloat16(a - __bfloat162float(h0));
  pl.y = __float2bfloat16(b - __bfloat162float(h1));
  *(__nv_bfloat162*)&oh[ofs] = ph;
  *(__nv_bfloat162*)&ol[ofs] = pl;
}
__device__ __forceinline__ void st_split1(__nv_bfloat16* oh, __nv_bfloat16* ol,
                                          size_t ofs, float a) {
  __nv_bfloat16 h0 = __float2bfloat16(a);
  oh[ofs] = h0;
  ol[ofs] = __float2bfloat16(a - __bfloat162float(h0));
}

// =======================================================================
// prep kernels
// =======================================================================
__global__ __launch_bounds__(256) void split_mat(const float* __restrict__ in,
                                                 int n, int which) {
  __nv_bfloat16* oh = which ? g_kvsh : g_qsh;
  __nv_bfloat16* ol = which ? g_kvsl : g_qsl;
  int j = (blockIdx.x * 256 + threadIdx.x) * 2;
  if (j < n) {
    float2 v = *(const float2*)&in[j];
    st_split(oh, ol, j, v.x, v.y);
  }
}

__global__ __launch_bounds__(256) void wtrans(const float* __restrict__ w,
                                              float scale, int which) {
  int j = (blockIdx.x * 256 + threadIdx.x) * 2;
  int nn = j >> 9, kk = j & 511;
  float a = w[kk * 512 + nn] * scale;
  float b = w[(kk + 1) * 512 + nn] * scale;
  st_split(&g_wth[which][0], &g_wtl[which][0], j, a, b);
}

__global__ __launch_bounds__(256) void mask_bits(const int* __restrict__ mask) {
  int w = blockIdx.x * 256 + threadIdx.x;  // word index < B*S*S/32
  const int* base = mask + (size_t)w * 32;
  uint32_t bits = 0;
#pragma unroll
  for (int t = 0; t < 32; t += 4) {
    int4 v = *(const int4*)&base[t];
    bits |= (v.x > 0 ? 1u : 0u) << t;
    bits |= (v.y > 0 ? 1u : 0u) << (t + 1);
    bits |= (v.z > 0 ? 1u : 0u) << (t + 2);
    bits |= (v.w > 0 ? 1u : 0u) << (t + 3);
  }
  g_mbits[w] = bits;
}

__global__ __launch_bounds__(256) void emb2_kernel(const float* __restrict__ rel,
                                                   const float* __restrict__ Wrel) {
  __shared__ float w[32][33];
  int tid = threadIdx.x;
  for (int i = tid; i < 32 * 32; i += 256) w[i >> 5][i & 31] = Wrel[i];
  __syncthreads();
  int d = tid & 31;
  int tl = tid >> 5;
  int t = blockIdx.x * 8 + tl;
  if (t < 2 * S + 1) {
    float s = 0.f;
#pragma unroll
    for (int j = 0; j < 32; j++) s += rel[t * 32 + j] * w[j][d];
    g_emb2h[t * D + d] = __float2bfloat16(s);
  }
}

// =======================================================================
// Copy-fill split-bf16 GEMM. mode 0: Q (scaled W), 1: K, 2: V (TRANSPOSED
// per-head scatter [b,h,d,s]), 3: ctx @ Wo -> fp32 out.
// =======================================================================
__global__ __launch_bounds__(256) void gemm_bf16(float* __restrict__ outp, int mode) {
  __shared__ __nv_bfloat16 Ah[128][40];
  __shared__ __nv_bfloat16 Al[128][40];
  __shared__ __nv_bfloat16 Bh[64][40];
  __shared__ __nv_bfloat16 Bl[64][40];

  const __nv_bfloat16* ash = (mode == 0) ? g_qsh : (mode == 3) ? g_ctxh : g_kvsh;
  const __nv_bfloat16* asl = (mode == 0) ? g_qsl : (mode == 3) ? g_ctxl : g_kvsl;
  const __nv_bfloat16* bth = &g_wth[mode][0];
  const __nv_bfloat16* btl = &g_wtl[mode][0];

  int tid = threadIdx.x, wid = tid >> 5, lane = tid & 31;
  int wm = wid >> 1, wn = wid & 1;
  int m0 = blockIdx.y * 128, n0 = blockIdx.x * 64;
  int r = lane >> 2, c2 = (lane & 3) * 2;

  float acc[2][4][4];
#pragma unroll
  for (int mt = 0; mt < 2; mt++)
#pragma unroll
    for (int nt = 0; nt < 4; nt++)
#pragma unroll
      for (int i = 0; i < 4; i++) acc[mt][nt][i] = 0.f;

  for (int c = 0; c < 16; c++) {
    int k0 = c * 32;
#pragma unroll
    for (int u = 0; u < 2; u++) {
      int i = tid + u * 256;
      int rr = i >> 2, c8 = (i & 3) * 8;
      size_t src = (size_t)(m0 + rr) * 512 + k0 + c8;
      *(uint4*)&Ah[rr][c8] = *(const uint4*)&ash[src];
      *(uint4*)&Al[rr][c8] = *(const uint4*)&asl[src];
    }
    {
      int nn = tid >> 2, c8 = (tid & 3) * 8;
      size_t src = (size_t)(n0 + nn) * 512 + k0 + c8;
      *(uint4*)&Bh[nn][c8] = *(const uint4*)&bth[src];
      *(uint4*)&Bl[nn][c8] = *(const uint4*)&btl[src];
    }
    __syncthreads();

#pragma unroll
    for (int ks = 0; ks < 2; ks++) {
      int kk = ks * 16;
      uint32_t ah[2][4], al[2][4];
#pragma unroll
      for (int mt = 0; mt < 2; mt++) {
        int rb = wm * 32 + mt * 16;
        ah[mt][0] = *(const uint32_t*)&Ah[rb + r][kk + c2];
        ah[mt][1] = *(const uint32_t*)&Ah[rb + r + 8][kk + c2];
        ah[mt][2] = *(const uint32_t*)&Ah[rb + r][kk + c2 + 8];
        ah[mt][3] = *(const uint32_t*)&Ah[rb + r + 8][kk + c2 + 8];
        al[mt][0] = *(const uint32_t*)&Al[rb + r][kk + c2];
        al[mt][1] = *(const uint32_t*)&Al[rb + r + 8][kk + c2];
        al[mt][2] = *(const uint32_t*)&Al[rb + r][kk + c2 + 8];
        al[mt][3] = *(const uint32_t*)&Al[rb + r + 8][kk + c2 + 8];
      }
      uint32_t bh[4][2], bl[4][2];
#pragma unroll
      for (int nt = 0; nt < 4; nt++) {
        int nb = wn * 32 + nt * 8 + r;
        bh[nt][0] = *(const uint32_t*)&Bh[nb][kk + c2];
        bh[nt][1] = *(const uint32_t*)&Bh[nb][kk + c2 + 8];
        bl[nt][0] = *(const uint32_t*)&Bl[nb][kk + c2];
        bl[nt][1] = *(const uint32_t*)&Bl[nb][kk + c2 + 8];
      }
#pragma unroll
      for (int mt = 0; mt < 2; mt++)
#pragma unroll
        for (int nt = 0; nt < 4; nt++) {
          MMA16816(acc[mt][nt], ah[mt], bh[nt][0], bh[nt][1]);
          MMA16816(acc[mt][nt], ah[mt], bl[nt][0], bl[nt][1]);
          MMA16816(acc[mt][nt], al[mt], bh[nt][0], bh[nt][1]);
        }
    }
    __syncthreads();
  }

#pragma unroll
  for (int mt = 0; mt < 2; mt++)
#pragma unroll
    for (int nt = 0; nt < 4; nt++) {
      int m = m0 + wm * 32 + mt * 16 + r;
      int n = n0 + wn * 32 + nt * 8 + c2;
      if (mode == 2) {  // V: transposed scatter [b,h,d,s]
        int hh = n >> 5, dd = n & 31;
        int bb = m >> 10, ss = m & 1023;
        size_t o00 = (((size_t)(bb * H + hh)) * D + dd) * S + ss;
        st_split1(g_vth, g_vtl, o00, acc[mt][nt][0]);
        st_split1(g_vth, g_vtl, o00 + S, acc[mt][nt][1]);   // dd+1
        int m8 = m + 8, bb8 = m8 >> 10, ss8 = m8 & 1023;
        size_t o10 = (((size_t)(bb8 * H + hh)) * D + dd) * S + ss8;
        st_split1(g_vth, g_vtl, o10, acc[mt][nt][2]);
        st_split1(g_vth, g_vtl, o10 + S, acc[mt][nt][3]);
      } else if (mode < 2) {
        __nv_bfloat16* oh = (mode == 0) ? g_qhh : g_khh;
        __nv_bfloat16* ol = (mode == 0) ? g_qhl : g_khl;
        int hh = n >> 5, dd = n & 31;
        int bb = m >> 10, ss = m & 1023;
        size_t o0 = (((size_t)(bb * H + hh)) * S + ss) * D + dd;
        st_split(oh, ol, o0, acc[mt][nt][0], acc[mt][nt][1]);
        int m8 = m + 8, bb8 = m8 >> 10, ss8 = m8 & 1023;
        size_t o1 = (((size_t)(bb8 * H + hh)) * S + ss8) * D + dd;
        st_split(oh, ol, o1, acc[mt][nt][2], acc[mt][nt][3]);
      } else {
        *(float2*)&outp[(size_t)m * 512 + n] = make_float2(acc[mt][nt][0], acc[mt][nt][1]);
        *(float2*)&outp[(size_t)(m + 8) * 512 + n] = make_float2(acc[mt][nt][2], acc[mt][nt][3]);
      }
    }
}

// =======================================================================
// MMA flash attention. All fills uint4 copies; mask from bit-packed gmem.
// smem 46KB -> 4 CTAs/SM. Grid (16 qb, 16 h, 4 b), 128 threads.
// =======================================================================
#define AT_KH   0
#define AT_KL   15360
#define AT_VTH  20480
#define AT_VTL  25088
#define AT_BI   29696
#define AT_SMEM 47104

__global__ __launch_bounds__(128, 4) void attn_mma() {
  extern __shared__ char sm[];
  __nv_bfloat16* KH  = (__nv_bfloat16*)(sm + AT_KH);   // [192][40]
  __nv_bfloat16* KL  = (__nv_bfloat16*)(sm + AT_KL);   // [64][40]
  __nv_bfloat16* VTH = (__nv_bfloat16*)(sm + AT_VTH);  // [32][72]
  __nv_bfloat16* VTL = (__nv_bfloat16*)(sm + AT_VTL);
  __half*        BI  = (__half*)(sm + AT_BI);          // [64][136]

  int tid = threadIdx.x, wid = tid >> 5, lane = tid & 31;
  int r = lane >> 2, c2 = (lane & 3) * 2;
  int qb = blockIdx.x, h = blockIdx.y, b = blockIdx.z;
  int q0 = qb * 64, wq = wid * 16;
  size_t bh = (size_t)(b * H + h);

  // Q fragments from gmem (pre-scaled, pre-split)
  uint32_t aH[2][4], aL[2][4];
  {
    size_t rowa = (bh * S + q0 + wq + r) * D;
    size_t rowb = (bh * S + q0 + wq + r + 8) * D;
#pragma unroll
    for (int ch = 0; ch < 2; ch++) {
      int cb = ch * 16 + c2;
      aH[ch][0] = *(const uint32_t*)&g_qhh[rowa + cb];
      aH[ch][1] = *(const uint32_t*)&g_qhh[rowb + cb];
      aH[ch][2] = *(const uint32_t*)&g_qhh[rowa + cb + 8];
      aH[ch][3] = *(const uint32_t*)&g_qhh[rowb + cb + 8];
      aL[ch][0] = *(const uint32_t*)&g_qhl[rowa + cb];
      aL[ch][1] = *(const uint32_t*)&g_qhl[rowb + cb];
      aL[ch][2] = *(const uint32_t*)&g_qhl[rowa + cb + 8];
      aL[ch][3] = *(const uint32_t*)&g_qhl[rowb + cb + 8];
    }
  }

  float O[4][4];
#pragma unroll
  for (int nt = 0; nt < 4; nt++)
#pragma unroll
    for (int i = 0; i < 4; i++) O[nt][i] = 0.f;
  float mo0 = -INFINITY, mo1 = -INFINITY, lo0 = 0.f, lo1 = 0.f;

  int qa = wq + r, qbx = qa + 8;
  size_t mrow0 = ((size_t)b * S + q0 + qa) * S;   // bits base, row qa
  size_t mrow1 = ((size_t)b * S + q0 + qbx) * S;

  for (int k0 = 0; k0 < S; k0 += 64) {
    __syncthreads();
    // K rows 0..63 (hi+lo): uint4 copies
    for (int i = tid; i < 256; i += 128) {
      int row = i >> 2, c8 = (i & 3) * 8;
      size_t g = (bh * S + k0 + row) * D + c8;
      *(uint4*)&KH[row * 40 + c8] = *(const uint4*)&g_khh[g];
      *(uint4*)&KL[row * 40 + c8] = *(const uint4*)&g_khl[g];
    }
    // emb2 window rows 64..190 (hi only; row 191 zero)
    int tb = k0 - q0 + S - 63;
    for (int i = tid; i < 512; i += 128) {
      int rr = i >> 2, c8 = (i & 3) * 8;
      uint4 vh = make_uint4(0, 0, 0, 0);
      if (rr < 127) vh = *(const uint4*)&g_emb2h[(size_t)(tb + rr) * D + c8];
      *(uint4*)&KH[(64 + rr) * 40 + c8] = vh;
    }
    // V^T rows 0..31 (pre-transposed in gmem): uint4 copies
    for (int i = tid; i < 256; i += 128) {
      int d = i >> 3, c8 = (i & 7) * 8;
      size_t g = (bh * D + d) * S + k0 + c8;
      *(uint4*)&VTH[d * 72 + c8] = *(const uint4*)&g_vth[g];
      *(uint4*)&VTL[d * 72 + c8] = *(const uint4*)&g_vtl[g];
    }
    __syncthreads();

    // mask bits for this tile (2 words per row)
    uint64_t mw0, mw1;
    {
      size_t w0 = (mrow0 + k0) >> 5, w1 = (mrow1 + k0) >> 5;
      mw0 = (uint64_t)g_mbits[w0] | ((uint64_t)g_mbits[w0 + 1] << 32);
      mw1 = (uint64_t)g_mbits[w1] | ((uint64_t)g_mbits[w1 + 1] << 32);
    }

    // content scores: 8 tiles, 3-pass
    float Cf[8][4];
#pragma unroll
    for (int j = 0; j < 8; j++) {
#pragma unroll
      for (int i = 0; i < 4; i++) Cf[j][i] = 0.f;
#pragma unroll
      for (int ch = 0; ch < 2; ch++) {
        int ro = (j * 8 + r) * 40 + ch * 16 + c2;
        uint32_t b0h = *(const uint32_t*)&KH[ro];
        uint32_t b1h = *(const uint32_t*)&KH[ro + 8];
        uint32_t b0l = *(const uint32_t*)&KL[ro];
        uint32_t b1l = *(const uint32_t*)&KL[ro + 8];
        MMA16816(Cf[j], aH[ch], b0h, b1h);
        MMA16816(Cf[j], aH[ch], b0l, b1l);
        MMA16816(Cf[j], aL[ch], b0h, b1h);
      }
    }
    // bias tiles: 1-pass, stash fp16
#pragma unroll
    for (int j = 8; j < 24; j++) {
      float Cb[4] = {0.f, 0.f, 0.f, 0.f};
#pragma unroll
      for (int ch = 0; ch < 2; ch++) {
        int ro = (j * 8 + r) * 40 + ch * 16 + c2;
        uint32_t b0h = *(const uint32_t*)&KH[ro];
        uint32_t b1h = *(const uint32_t*)&KH[ro + 8];
        MMA16816(Cb, aH[ch], b0h, b1h);
      }
      int tl = (j - 8) * 8 + c2;
      uint32_t p0, p1;
      CVTF16X2(p0, Cb[1], Cb[0]);
      CVTF16X2(p1, Cb[3], Cb[2]);
      *(uint32_t*)&BI[qa * 136 + tl] = p0;
      *(uint32_t*)&BI[qbx * 136 + tl] = p1;
    }
    __syncwarp();

    // softmax
    float tm0 = -INFINITY, tm1 = -INFINITY;
#pragma unroll
    for (int j = 0; j < 8; j++)
#pragma unroll
      for (int e = 0; e < 2; e++) {
        int kk = 8 * j + c2 + e;
        float s0 = Cf[j][e] + __half2float(BI[qa * 136 + kk - qa + 63]);
        if (!((mw0 >> kk) & 1)) s0 = -INFINITY;
        Cf[j][e] = s0;
        tm0 = fmaxf(tm0, s0);
        float s1 = Cf[j][2 + e] + __half2float(BI[qbx * 136 + kk - qbx + 63]);
        if (!((mw1 >> kk) & 1)) s1 = -INFINITY;
        Cf[j][2 + e] = s1;
        tm1 = fmaxf(tm1, s1);
      }
    tm0 = fmaxf(tm0, __shfl_xor_sync(0xffffffffu, tm0, 1));
    tm0 = fmaxf(tm0, __shfl_xor_sync(0xffffffffu, tm0, 2));
    tm1 = fmaxf(tm1, __shfl_xor_sync(0xffffffffu, tm1, 1));
    tm1 = fmaxf(tm1, __shfl_xor_sync(0xffffffffu, tm1, 2));
    float mn0 = fmaxf(mo0, tm0), mn1 = fmaxf(mo1, tm1);
    float base0 = (mn0 == -INFINITY) ? 0.f : mn0;
    float base1 = (mn1 == -INFINITY) ? 0.f : mn1;
    float corr0 = (mo0 == -INFINITY) ? 0.f : __expf(mo0 - mn0);
    float corr1 = (mo1 == -INFINITY) ? 0.f : __expf(mo1 - mn1);
    float ls0 = 0.f, ls1 = 0.f;
#pragma unroll
    for (int j = 0; j < 8; j++)
#pragma unroll
      for (int e = 0; e < 2; e++) {
        float p0 = __expf(Cf[j][e] - base0);
        Cf[j][e] = p0; ls0 += p0;
        float p1 = __expf(Cf[j][2 + e] - base1);
        Cf[j][2 + e] = p1; ls1 += p1;
      }
    ls0 += __shfl_xor_sync(0xffffffffu, ls0, 1);
    ls0 += __shfl_xor_sync(0xffffffffu, ls0, 2);
    ls1 += __shfl_xor_sync(0xffffffffu, ls1, 1);
    ls1 += __shfl_xor_sync(0xffffffffu, ls1, 2);
    lo0 = lo0 * corr0 + ls0;
    lo1 = lo1 * corr1 + ls1;
    mo0 = mn0; mo1 = mn1;
#pragma unroll
    for (int nt = 0; nt < 4; nt++) {
      O[nt][0] *= corr0; O[nt][1] *= corr0;
      O[nt][2] *= corr1; O[nt][3] *= corr1;
    }

    // PV: split P @ V^T, 3-pass
#pragma unroll
    for (int ch = 0; ch < 4; ch++) {
      uint32_t ph[4], pl[4];
#pragma unroll
      for (int half = 0; half < 2; half++) {
        float plo = Cf[2 * ch][2 * half + 0], phi = Cf[2 * ch][2 * half + 1];
        uint32_t pk; CVT2(pk, phi, plo);
        ph[half] = pk;
        float rlo = plo - __uint_as_float(pk << 16);
        float rhi = phi - __uint_as_float(pk & 0xffff0000u);
        CVT2(pl[half], rhi, rlo);
        plo = Cf[2 * ch + 1][2 * half + 0]; phi = Cf[2 * ch + 1][2 * half + 1];
        CVT2(pk, phi, plo);
        ph[2 + half] = pk;
        rlo = plo - __uint_as_float(pk << 16);
        rhi = phi - __uint_as_float(pk & 0xffff0000u);
        CVT2(pl[2 + half], rhi, rlo);
      }
      uint32_t pA[4] = {ph[0], ph[1], ph[2], ph[3]};
      uint32_t pB[4] = {pl[0], pl[1], pl[2], pl[3]};
#pragma unroll
      for (int nt = 0; nt < 4; nt++) {
        int ro = (nt * 8 + r) * 72 + ch * 16 + c2;
        uint32_t b0h = *(const uint32_t*)&VTH[ro];
        uint32_t b1h = *(const uint32_t*)&VTH[ro + 8];
        uint32_t b0l = *(const uint32_t*)&VTL[ro];
        uint32_t b1l = *(const uint32_t*)&VTL[ro + 8];
        MMA16816(O[nt], pA, b0h, b1h);
        MMA16816(O[nt], pA, b0l, b1l);
        MMA16816(O[nt], pB, b0h, b1h);
      }
    }
  }

  // epilogue -> split ctx
  float inv0 = 1.f / lo0, inv1 = 1.f / lo1;
  int qg0 = q0 + qa, qg1 = q0 + qbx;
#pragma unroll
  for (int nt = 0; nt < 4; nt++) {
    int col = h * 32 + nt * 8 + c2;
    st_split(g_ctxh, g_ctxl, ((size_t)b * S + qg0) * F + col,
             O[nt][0] * inv0, O[nt][1] * inv0);
    st_split(g_ctxh, g_ctxl, ((size_t)b * S + qg1) * F + col,
             O[nt][2] * inv1, O[nt][3] * inv1);
  }
}

// =======================================================================
// Host launch: identify inputs by SIZE (proven).
// =======================================================================
extern "C" void kernel_launch(void* const* d_in, const int* in_sizes, int n_in,
                              void* d_out, int out_size) {
  const float* big2m[2] = {nullptr, nullptr};
  const float* w512[4]  = {nullptr, nullptr, nullptr, nullptr};
  const int*   mask = nullptr;
  const float* rel = nullptr;
  const float* Wrel = nullptr;
  int nbig = 0, nw = 0;

  for (int i = 0; i < n_in; i++) {
    int sz = in_sizes[i];
    if (sz == B * S * F) {
      if (nbig < 2) big2m[nbig++] = (const float*)d_in[i];
    } else if (sz == B * S * S) {
      mask = (const int*)d_in[i];
    } else if (sz == F * F) {
      if (nw < 4) w512[nw++] = (const float*)d_in[i];
    } else if (sz == (2 * S + 1) * D) {
      rel = (const float*)d_in[i];
    } else if (sz == D * D) {
      Wrel = (const float*)d_in[i];
    }
  }

  const float* kv = big2m[0];
  const float* q  = big2m[1];

  const float *Wq, *Wk, *Wv, *Wo;
  if (n_in > 0 && in_sizes[0] == B * S * F) {
    Wq = w512[0]; Wk = w512[1]; Wv = w512[2]; Wo = w512[3];
  } else {
    Wk = w512[0]; Wo = w512[1]; Wq = w512[2]; Wv = w512[3];
  }

  float* out = (float*)d_out;

  static int smem_set = 0;
  if (!smem_set) {
    cudaFuncSetAttribute(attn_mma, cudaFuncAttributeMaxDynamicSharedMemorySize, AT_SMEM);
    smem_set = 1;
  }

  // prep
  split_mat<<<4096, 256>>>(q, M * F, 0);
  split_mat<<<4096, 256>>>(kv, M * F, 1);
  wtrans<<<512, 256>>>(Wq, 0.17677669529663687f, 0);
  wtrans<<<512, 256>>>(Wk, 1.0f, 1);
  wtrans<<<512, 256>>>(Wv, 1.0f, 2);
  wtrans<<<512, 256>>>(Wo, 1.0f, 3);
  mask_bits<<<512, 256>>>(mask);
  emb2_kernel<<<257, 256>>>(rel, Wrel);

  dim3 gg(512 / 64, M / 128);  // (8, 32)
  gemm_bf16<<<gg, 256>>>(nullptr, 0);  // -> split qh (scaled)
  gemm_bf16<<<gg, 256>>>(nullptr, 1);  // -> split kh
  gemm_bf16<<<gg, 256>>>(nullptr, 2);  // -> split V^T

  attn_mma<<<dim3(16, 16, 4), 128, AT_SMEM>>>();  // -> split ctx

  gemm_bf16<<<gg, 256>>>(out, 3);      // ctx @ Wo -> d_out
}

// round 17
// speedup vs baseline: 3.5237x; 1.0855x over previous
#include <cuda_runtime.h>
#include <cuda_bf16.h>
#include <cstdint>
#include <math.h>

#define B 4
#define S 1024
#define F 512
#define H 16
#define D 32
#define M (B*S)

// -------- scratch (no allocations allowed) --------
__device__ __nv_bfloat16 g_qsh[M*F],  g_qsl[M*F];      // split q input
__device__ __nv_bfloat16 g_kvsh[M*F], g_kvsl[M*F];     // split kv input
__device__ __nv_bfloat16 g_wth[4][F*F], g_wtl[4][F*F]; // split W^T [n][k]
__device__ __nv_bfloat16 g_qhh[B*H*S*D], g_qhl[B*H*S*D];
__device__ __nv_bfloat16 g_khh[B*H*S*D], g_khl[B*H*S*D];
__device__ __nv_bfloat16 g_vth[B*H*D*S], g_vtl[B*H*D*S]; // V transposed [b,h,d,s]
__device__ __nv_bfloat16 g_emb2h[(2*S+1)*D];
__device__ __nv_bfloat16 g_ctxh[B*S*F], g_ctxl[B*S*F];
__device__ uint32_t g_mbits[B*S*S/32];                 // packed mask bits

// m16n8k16 bf16 MMA, fp32 accum (HMMA, baseline PTX)
#define MMA16816(cc, a, b0v, b1v)                                               \
  asm volatile("mma.sync.aligned.m16n8k16.row.col.f32.bf16.bf16.f32 "           \
               "{%0,%1,%2,%3}, {%4,%5,%6,%7}, {%8,%9}, {%0,%1,%2,%3};"          \
               : "+f"((cc)[0]), "+f"((cc)[1]), "+f"((cc)[2]), "+f"((cc)[3])     \
               : "r"((a)[0]), "r"((a)[1]), "r"((a)[2]), "r"((a)[3]),            \
                 "r"(b0v), "r"(b1v))

#define CVT2(d, hi, lo) \
  asm("cvt.rn.bf16x2.f32 %0, %1, %2;" : "=r"(d) : "f"(hi), "f"(lo))
#define CVTF16X2(d, hi, lo) \
  asm("cvt.rn.f16x2.f32 %0, %1, %2;" : "=r"(d) : "f"(hi), "f"(lo))

__device__ __forceinline__ void st_split(__nv_bfloat16* oh, __nv_bfloat16* ol,
                                         size_t ofs, float a, float b) {
  __nv_bfloat16 h0 = __float2bfloat16(a), h1 = __float2bfloat16(b);
  __nv_bfloat162 ph; ph.x = h0; ph.y = h1;
  __nv_bfloat162 pl;
  pl.x = __float2bfloat16(a - __bfloat162float(h0));
  pl.y = __float2bfloat16(b - __bfloat162float(h1));
  *(__nv_bfloat162*)&oh[ofs] = ph;
  *(__nv_bfloat162*)&ol[ofs] = pl;
}
__device__ __forceinline__ void st_split1(__nv_bfloat16* oh, __nv_bfloat16* ol,
                                          size_t ofs, float a) {
  __nv_bfloat16 h0 = __float2bfloat16(a);
  oh[ofs] = h0;
  ol[ofs] = __float2bfloat16(a - __bfloat162float(h0));
}

// =======================================================================
// prep kernels (fused)
// =======================================================================
// q and kv split in ONE launch: grid (4096, 2)
__global__ __launch_bounds__(256) void split_mat(const float* __restrict__ q,
                                                 const float* __restrict__ kv) {
  int which = blockIdx.y;
  const float* in = which ? kv : q;
  __nv_bfloat16* oh = which ? g_kvsh : g_qsh;
  __nv_bfloat16* ol = which ? g_kvsl : g_qsl;
  int j = (blockIdx.x * 256 + threadIdx.x) * 2;
  float2 v = *(const float2*)&in[j];
  st_split(oh, ol, j, v.x, v.y);
}

// all 4 W^T in ONE launch with coalesced smem transpose: grid (8, 8, 4)
__global__ __launch_bounds__(256) void wtrans_all(const float* __restrict__ w0,
                                                  const float* __restrict__ w1,
                                                  const float* __restrict__ w2,
                                                  const float* __restrict__ w3) {
  __shared__ float tile[64][65];
  int which = blockIdx.z;
  const float* w = (which == 0) ? w0 : (which == 1) ? w1 : (which == 2) ? w2 : w3;
  float scale = (which == 0) ? 0.17677669529663687f : 1.0f;
  int k0 = blockIdx.x * 64, n0 = blockIdx.y * 64;
  int tid = threadIdx.x;
  // coalesced read: w[k0+rr][n0+cc]
#pragma unroll
  for (int u = 0; u < 16; u++) {
    int idx = u * 256 + tid;
    int rr = idx >> 6, cc = idx & 63;
    tile[rr][cc] = w[(size_t)(k0 + rr) * 512 + n0 + cc] * scale;
  }
  __syncthreads();
  // coalesced write: out[n0+rr][k0+cc] = tile[cc][rr]
#pragma unroll
  for (int u = 0; u < 16; u++) {
    int idx = u * 256 + tid;
    int rr = idx >> 6, cc = idx & 63;
    st_split1(&g_wth[which][0], &g_wtl[which][0],
              (size_t)(n0 + rr) * 512 + k0 + cc, tile[cc][rr]);
  }
}

__global__ __launch_bounds__(256) void mask_bits(const int* __restrict__ mask) {
  int w = blockIdx.x * 256 + threadIdx.x;
  const int* base = mask + (size_t)w * 32;
  uint32_t bits = 0;
#pragma unroll
  for (int t = 0; t < 32; t += 4) {
    int4 v = *(const int4*)&base[t];
    bits |= (v.x > 0 ? 1u : 0u) << t;
    bits |= (v.y > 0 ? 1u : 0u) << (t + 1);
    bits |= (v.z > 0 ? 1u : 0u) << (t + 2);
    bits |= (v.w > 0 ? 1u : 0u) << (t + 3);
  }
  g_mbits[w] = bits;
}

__global__ __launch_bounds__(256) void emb2_kernel(const float* __restrict__ rel,
                                                   const float* __restrict__ Wrel) {
  __shared__ float w[32][33];
  int tid = threadIdx.x;
  for (int i = tid; i < 32 * 32; i += 256) w[i >> 5][i & 31] = Wrel[i];
  __syncthreads();
  int d = tid & 31;
  int tl = tid >> 5;
  int t = blockIdx.x * 8 + tl;
  if (t < 2 * S + 1) {
    float s = 0.f;
#pragma unroll
    for (int j = 0; j < 32; j++) s += rel[t * 32 + j] * w[j][d];
    g_emb2h[t * D + d] = __float2bfloat16(s);
  }
}

// =======================================================================
// Copy-fill split-bf16 GEMM. mode 0: Q (scaled W), 1: K, 2: V^T scatter,
// 3: ctx @ Wo -> fp32 out. QKV fused in one launch via blockIdx.z.
// =======================================================================
__global__ __launch_bounds__(256) void gemm_bf16(float* __restrict__ outp, int mode_in) {
  __shared__ __nv_bfloat16 Ah[128][40];
  __shared__ __nv_bfloat16 Al[128][40];
  __shared__ __nv_bfloat16 Bh[64][40];
  __shared__ __nv_bfloat16 Bl[64][40];

  int mode = (mode_in < 0) ? blockIdx.z : mode_in;
  const __nv_bfloat16* ash = (mode == 0) ? g_qsh : (mode == 3) ? g_ctxh : g_kvsh;
  const __nv_bfloat16* asl = (mode == 0) ? g_qsl : (mode == 3) ? g_ctxl : g_kvsl;
  const __nv_bfloat16* bth = &g_wth[mode][0];
  const __nv_bfloat16* btl = &g_wtl[mode][0];

  int tid = threadIdx.x, wid = tid >> 5, lane = tid & 31;
  int wm = wid >> 1, wn = wid & 1;
  int m0 = blockIdx.y * 128, n0 = blockIdx.x * 64;
  int r = lane >> 2, c2 = (lane & 3) * 2;

  float acc[2][4][4];
#pragma unroll
  for (int mt = 0; mt < 2; mt++)
#pragma unroll
    for (int nt = 0; nt < 4; nt++)
#pragma unroll
      for (int i = 0; i < 4; i++) acc[mt][nt][i] = 0.f;

  for (int c = 0; c < 16; c++) {
    int k0 = c * 32;
#pragma unroll
    for (int u = 0; u < 2; u++) {
      int i = tid + u * 256;
      int rr = i >> 2, c8 = (i & 3) * 8;
      size_t src = (size_t)(m0 + rr) * 512 + k0 + c8;
      *(uint4*)&Ah[rr][c8] = *(const uint4*)&ash[src];
      *(uint4*)&Al[rr][c8] = *(const uint4*)&asl[src];
    }
    {
      int nn = tid >> 2, c8 = (tid & 3) * 8;
      size_t src = (size_t)(n0 + nn) * 512 + k0 + c8;
      *(uint4*)&Bh[nn][c8] = *(const uint4*)&bth[src];
      *(uint4*)&Bl[nn][c8] = *(const uint4*)&btl[src];
    }
    __syncthreads();

#pragma unroll
    for (int ks = 0; ks < 2; ks++) {
      int kk = ks * 16;
      uint32_t ah[2][4], al[2][4];
#pragma unroll
      for (int mt = 0; mt < 2; mt++) {
        int rb = wm * 32 + mt * 16;
        ah[mt][0] = *(const uint32_t*)&Ah[rb + r][kk + c2];
        ah[mt][1] = *(const uint32_t*)&Ah[rb + r + 8][kk + c2];
        ah[mt][2] = *(const uint32_t*)&Ah[rb + r][kk + c2 + 8];
        ah[mt][3] = *(const uint32_t*)&Ah[rb + r + 8][kk + c2 + 8];
        al[mt][0] = *(const uint32_t*)&Al[rb + r][kk + c2];
        al[mt][1] = *(const uint32_t*)&Al[rb + r + 8][kk + c2];
        al[mt][2] = *(const uint32_t*)&Al[rb + r][kk + c2 + 8];
        al[mt][3] = *(const uint32_t*)&Al[rb + r + 8][kk + c2 + 8];
      }
      uint32_t bh[4][2], bl[4][2];
#pragma unroll
      for (int nt = 0; nt < 4; nt++) {
        int nb = wn * 32 + nt * 8 + r;
        bh[nt][0] = *(const uint32_t*)&Bh[nb][kk + c2];
        bh[nt][1] = *(const uint32_t*)&Bh[nb][kk + c2 + 8];
        bl[nt][0] = *(const uint32_t*)&Bl[nb][kk + c2];
        bl[nt][1] = *(const uint32_t*)&Bl[nb][kk + c2 + 8];
      }
#pragma unroll
      for (int mt = 0; mt < 2; mt++)
#pragma unroll
        for (int nt = 0; nt < 4; nt++) {
          MMA16816(acc[mt][nt], ah[mt], bh[nt][0], bh[nt][1]);
          MMA16816(acc[mt][nt], ah[mt], bl[nt][0], bl[nt][1]);
          MMA16816(acc[mt][nt], al[mt], bh[nt][0], bh[nt][1]);
        }
    }
    __syncthreads();
  }

#pragma unroll
  for (int mt = 0; mt < 2; mt++)
#pragma unroll
    for (int nt = 0; nt < 4; nt++) {
      int m = m0 + wm * 32 + mt * 16 + r;
      int n = n0 + wn * 32 + nt * 8 + c2;
      if (mode == 2) {  // V: transposed scatter [b,h,d,s]
        int hh = n >> 5, dd = n & 31;
        int bb = m >> 10, ss = m & 1023;
        size_t o00 = (((size_t)(bb * H + hh)) * D + dd) * S + ss;
        st_split1(g_vth, g_vtl, o00, acc[mt][nt][0]);
        st_split1(g_vth, g_vtl, o00 + S, acc[mt][nt][1]);
        int m8 = m + 8, bb8 = m8 >> 10, ss8 = m8 & 1023;
        size_t o10 = (((size_t)(bb8 * H + hh)) * D + dd) * S + ss8;
        st_split1(g_vth, g_vtl, o10, acc[mt][nt][2]);
        st_split1(g_vth, g_vtl, o10 + S, acc[mt][nt][3]);
      } else if (mode < 2) {
        __nv_bfloat16* oh = (mode == 0) ? g_qhh : g_khh;
        __nv_bfloat16* ol = (mode == 0) ? g_qhl : g_khl;
        int hh = n >> 5, dd = n & 31;
        int bb = m >> 10, ss = m & 1023;
        size_t o0 = (((size_t)(bb * H + hh)) * S + ss) * D + dd;
        st_split(oh, ol, o0, acc[mt][nt][0], acc[mt][nt][1]);
        int m8 = m + 8, bb8 = m8 >> 10, ss8 = m8 & 1023;
        size_t o1 = (((size_t)(bb8 * H + hh)) * S + ss8) * D + dd;
        st_split(oh, ol, o1, acc[mt][nt][2], acc[mt][nt][3]);
      } else {
        *(float2*)&outp[(size_t)m * 512 + n] = make_float2(acc[mt][nt][0], acc[mt][nt][1]);
        *(float2*)&outp[(size_t)(m + 8) * 512 + n] = make_float2(acc[mt][nt][2], acc[mt][nt][3]);
      }
    }
}

// =======================================================================
// MMA flash attention. Warp-band bias: each warp computes only the 10
// window tiles covering its own 79-wide diagonal band.
// smem 46KB -> 4 CTAs/SM. Grid (16 qb, 16 h, 4 b), 128 threads.
// =======================================================================
#define AT_KH   0
#define AT_KL   15360
#define AT_VTH  20480
#define AT_VTL  25088
#define AT_BI   29696
#define AT_SMEM 47104

__global__ __launch_bounds__(128, 4) void attn_mma() {
  extern __shared__ char sm[];
  __nv_bfloat16* KH  = (__nv_bfloat16*)(sm + AT_KH);   // [192][40]
  __nv_bfloat16* KL  = (__nv_bfloat16*)(sm + AT_KL);   // [64][40]
  __nv_bfloat16* VTH = (__nv_bfloat16*)(sm + AT_VTH);  // [32][72]
  __nv_bfloat16* VTL = (__nv_bfloat16*)(sm + AT_VTL);
  __half*        BI  = (__half*)(sm + AT_BI);          // [64][136]

  int tid = threadIdx.x, wid = tid >> 5, lane = tid & 31;
  int r = lane >> 2, c2 = (lane & 3) * 2;
  int qb = blockIdx.x, h = blockIdx.y, b = blockIdx.z;
  int q0 = qb * 64, wq = wid * 16;
  size_t bh = (size_t)(b * H + h);

  // Q fragments from gmem
  uint32_t aH[2][4], aL[2][4];
  {
    size_t rowa = (bh * S + q0 + wq + r) * D;
    size_t rowb = (bh * S + q0 + wq + r + 8) * D;
#pragma unroll
    for (int ch = 0; ch < 2; ch++) {
      int cb = ch * 16 + c2;
      aH[ch][0] = *(const uint32_t*)&g_qhh[rowa + cb];
      aH[ch][1] = *(const uint32_t*)&g_qhh[rowb + cb];
      aH[ch][2] = *(const uint32_t*)&g_qhh[rowa + cb + 8];
      aH[ch][3] = *(const uint32_t*)&g_qhh[rowb + cb + 8];
      aL[ch][0] = *(const uint32_t*)&g_qhl[rowa + cb];
      aL[ch][1] = *(const uint32_t*)&g_qhl[rowb + cb];
      aL[ch][2] = *(const uint32_t*)&g_qhl[rowa + cb + 8];
      aL[ch][3] = *(const uint32_t*)&g_qhl[rowb + cb + 8];
    }
  }

  float O[4][4];
#pragma unroll
  for (int nt = 0; nt < 4; nt++)
#pragma unroll
    for (int i = 0; i < 4; i++) O[nt][i] = 0.f;
  float mo0 = -INFINITY, mo1 = -INFINITY, lo0 = 0.f, lo1 = 0.f;

  int qa = wq + r, qbx = qa + 8;
  size_t mrow0 = ((size_t)b * S + q0 + qa) * S;
  size_t mrow1 = ((size_t)b * S + q0 + qbx) * S;
  int t0 = 6 - 2 * wid;  // first window tile this warp needs (wid 0..3 -> 6,4,2,0)

  for (int k0 = 0; k0 < S; k0 += 64) {
    __syncthreads();
    // K rows 0..63 (hi+lo)
    for (int i = tid; i < 256; i += 128) {
      int row = i >> 2, c8 = (i & 3) * 8;
      size_t g = (bh * S + k0 + row) * D + c8;
      *(uint4*)&KH[row * 40 + c8] = *(const uint4*)&g_khh[g];
      *(uint4*)&KL[row * 40 + c8] = *(const uint4*)&g_khl[g];
    }
    // emb2 window rows 64..190 (hi only; row 191 zero)
    int tb = k0 - q0 + S - 63;
    for (int i = tid; i < 512; i += 128) {
      int rr = i >> 2, c8 = (i & 3) * 8;
      uint4 vh = make_uint4(0, 0, 0, 0);
      if (rr < 127) vh = *(const uint4*)&g_emb2h[(size_t)(tb + rr) * D + c8];
      *(uint4*)&KH[(64 + rr) * 40 + c8] = vh;
    }
    // V^T rows 0..31 (pre-transposed)
    for (int i = tid; i < 256; i += 128) {
      int d = i >> 3, c8 = (i & 7) * 8;
      size_t g = (bh * D + d) * S + k0 + c8;
      *(uint4*)&VTH[d * 72 + c8] = *(const uint4*)&g_vth[g];
      *(uint4*)&VTL[d * 72 + c8] = *(const uint4*)&g_vtl[g];
    }
    __syncthreads();

    uint64_t mw0, mw1;
    {
      size_t w0 = (mrow0 + k0) >> 5, w1 = (mrow1 + k0) >> 5;
      mw0 = (uint64_t)g_mbits[w0] | ((uint64_t)g_mbits[w0 + 1] << 32);
      mw1 = (uint64_t)g_mbits[w1] | ((uint64_t)g_mbits[w1 + 1] << 32);
    }

    // content scores: 8 tiles, 3-pass
    float Cf[8][4];
#pragma unroll
    for (int j = 0; j < 8; j++) {
#pragma unroll
      for (int i = 0; i < 4; i++) Cf[j][i] = 0.f;
#pragma unroll
      for (int ch = 0; ch < 2; ch++) {
        int ro = (j * 8 + r) * 40 + ch * 16 + c2;
        uint32_t b0h = *(const uint32_t*)&KH[ro];
        uint32_t b1h = *(const uint32_t*)&KH[ro + 8];
        uint32_t b0l = *(const uint32_t*)&KL[ro];
        uint32_t b1l = *(const uint32_t*)&KL[ro + 8];
        MMA16816(Cf[j], aH[ch], b0h, b1h);
        MMA16816(Cf[j], aH[ch], b0l, b1l);
        MMA16816(Cf[j], aL[ch], b0h, b1h);
      }
    }
    // bias tiles: warp band only (10 of 16 tiles), 1-pass, stash fp16
#pragma unroll
    for (int tt = 0; tt < 10; tt++) {
      int t = t0 + tt;  // window tile 0..15
      float Cb[4] = {0.f, 0.f, 0.f, 0.f};
#pragma unroll
      for (int ch = 0; ch < 2; ch++) {
        int ro = ((64 + t * 8) + r) * 40 + ch * 16 + c2;
        uint32_t b0h = *(const uint32_t*)&KH[ro];
        uint32_t b1h = *(const uint32_t*)&KH[ro + 8];
        MMA16816(Cb, aH[ch], b0h, b1h);
      }
      int tl = t * 8 + c2;
      uint32_t p0, p1;
      CVTF16X2(p0, Cb[1], Cb[0]);
      CVTF16X2(p1, Cb[3], Cb[2]);
      *(uint32_t*)&BI[qa * 136 + tl] = p0;
      *(uint32_t*)&BI[qbx * 136 + tl] = p1;
    }
    __syncwarp();

    // softmax
    float tm0 = -INFINITY, tm1 = -INFINITY;
#pragma unroll
    for (int j = 0; j < 8; j++)
#pragma unroll
      for (int e = 0; e < 2; e++) {
        int kk = 8 * j + c2 + e;
        float s0 = Cf[j][e] + __half2float(BI[qa * 136 + kk - qa + 63]);
        if (!((mw0 >> kk) & 1)) s0 = -INFINITY;
        Cf[j][e] = s0;
        tm0 = fmaxf(tm0, s0);
        float s1 = Cf[j][2 + e] + __half2float(BI[qbx * 136 + kk - qbx + 63]);
        if (!((mw1 >> kk) & 1)) s1 = -INFINITY;
        Cf[j][2 + e] = s1;
        tm1 = fmaxf(tm1, s1);
      }
    tm0 = fmaxf(tm0, __shfl_xor_sync(0xffffffffu, tm0, 1));
    tm0 = fmaxf(tm0, __shfl_xor_sync(0xffffffffu, tm0, 2));
    tm1 = fmaxf(tm1, __shfl_xor_sync(0xffffffffu, tm1, 1));
    tm1 = fmaxf(tm1, __shfl_xor_sync(0xffffffffu, tm1, 2));
    float mn0 = fmaxf(mo0, tm0), mn1 = fmaxf(mo1, tm1);
    float base0 = (mn0 == -INFINITY) ? 0.f : mn0;
    float base1 = (mn1 == -INFINITY) ? 0.f : mn1;
    float corr0 = (mo0 == -INFINITY) ? 0.f : __expf(mo0 - mn0);
    float corr1 = (mo1 == -INFINITY) ? 0.f : __expf(mo1 - mn1);
    float ls0 = 0.f, ls1 = 0.f;
#pragma unroll
    for (int j = 0; j < 8; j++)
#pragma unroll
      for (int e = 0; e < 2; e++) {
        float p0 = __expf(Cf[j][e] - base0);
        Cf[j][e] = p0; ls0 += p0;
        float p1 = __expf(Cf[j][2 + e] - base1);
        Cf[j][2 + e] = p1; ls1 += p1;
      }
    ls0 += __shfl_xor_sync(0xffffffffu, ls0, 1);
    ls0 += __shfl_xor_sync(0xffffffffu, ls0, 2);
    ls1 += __shfl_xor_sync(0xffffffffu, ls1, 1);
    ls1 += __shfl_xor_sync(0xffffffffu, ls1, 2);
    lo0 = lo0 * corr0 + ls0;
    lo1 = lo1 * corr1 + ls1;
    mo0 = mn0; mo1 = mn1;
#pragma unroll
    for (int nt = 0; nt < 4; nt++) {
      O[nt][0] *= corr0; O[nt][1] *= corr0;
      O[nt][2] *= corr1; O[nt][3] *= corr1;
    }

    // PV: split P @ V^T, 3-pass
#pragma unroll
    for (int ch = 0; ch < 4; ch++) {
      uint32_t ph[4], pl[4];
#pragma unroll
      for (int half = 0; half < 2; half++) {
        float plo = Cf[2 * ch][2 * half + 0], phi = Cf[2 * ch][2 * half + 1];
        uint32_t pk; CVT2(pk, phi, plo);
        ph[half] = pk;
        float rlo = plo - __uint_as_float(pk << 16);
        float rhi = phi - __uint_as_float(pk & 0xffff0000u);
        CVT2(pl[half], rhi, rlo);
        plo = Cf[2 * ch + 1][2 * half + 0]; phi = Cf[2 * ch + 1][2 * half + 1];
        CVT2(pk, phi, plo);
        ph[2 + half] = pk;
        rlo = plo - __uint_as_float(pk << 16);
        rhi = phi - __uint_as_float(pk & 0xffff0000u);
        CVT2(pl[2 + half], rhi, rlo);
      }
      uint32_t pA[4] = {ph[0], ph[1], ph[2], ph[3]};
      uint32_t pB[4] = {pl[0], pl[1], pl[2], pl[3]};
#pragma unroll
      for (int nt = 0; nt < 4; nt++) {
        int ro = (nt * 8 + r) * 72 + ch * 16 + c2;
        uint32_t b0h = *(const uint32_t*)&VTH[ro];
        uint32_t b1h = *(const uint32_t*)&VTH[ro + 8];
        uint32_t b0l = *(const uint32_t*)&VTL[ro];
        uint32_t b1l = *(const uint32_t*)&VTL[ro + 8];
        MMA16816(O[nt], pA, b0h, b1h);
        MMA16816(O[nt], pA, b0l, b1l);
        MMA16816(O[nt], pB, b0h, b1h);
      }
    }
  }

  // epilogue -> split ctx
  float inv0 = 1.f / lo0, inv1 = 1.f / lo1;
  int qg0 = q0 + qa, qg1 = q0 + qbx;
#pragma unroll
  for (int nt = 0; nt < 4; nt++) {
    int col = h * 32 + nt * 8 + c2;
    st_split(g_ctxh, g_ctxl, ((size_t)b * S + qg0) * F + col,
             O[nt][0] * inv0, O[nt][1] * inv0);
    st_split(g_ctxh, g_ctxl, ((size_t)b * S + qg1) * F + col,
             O[nt][2] * inv1, O[nt][3] * inv1);
  }
}

// =======================================================================
// Host launch: identify inputs by SIZE (proven).
// =======================================================================
extern "C" void kernel_launch(void* const* d_in, const int* in_sizes, int n_in,
                              void* d_out, int out_size) {
  const float* big2m[2] = {nullptr, nullptr};
  const float* w512[4]  = {nullptr, nullptr, nullptr, nullptr};
  const int*   mask = nullptr;
  const float* rel = nullptr;
  const float* Wrel = nullptr;
  int nbig = 0, nw = 0;

  for (int i = 0; i < n_in; i++) {
    int sz = in_sizes[i];
    if (sz == B * S * F) {
      if (nbig < 2) big2m[nbig++] = (const float*)d_in[i];
    } else if (sz == B * S * S) {
      mask = (const int*)d_in[i];
    } else if (sz == F * F) {
      if (nw < 4) w512[nw++] = (const float*)d_in[i];
    } else if (sz == (2 * S + 1) * D) {
      rel = (const float*)d_in[i];
    } else if (sz == D * D) {
      Wrel = (const float*)d_in[i];
    }
  }

  const float* kv = big2m[0];
  const float* q  = big2m[1];

  const float *Wq, *Wk, *Wv, *Wo;
  if (n_in > 0 && in_sizes[0] == B * S * F) {
    Wq = w512[0]; Wk = w512[1]; Wv = w512[2]; Wo = w512[3];
  } else {
    Wk = w512[0]; Wo = w512[1]; Wq = w512[2]; Wv = w512[3];
  }

  float* out = (float*)d_out;

  static int smem_set = 0;
  if (!smem_set) {
    cudaFuncSetAttribute(attn_mma, cudaFuncAttributeMaxDynamicSharedMemorySize, AT_SMEM);
    smem_set = 1;
  }

  // prep (4 launches)
  split_mat<<<dim3(4096, 2), 256>>>(q, kv);
  wtrans_all<<<dim3(8, 8, 4), 256>>>(Wq, Wk, Wv, Wo);
  mask_bits<<<512, 256>>>(mask);
  emb2_kernel<<<257, 256>>>(rel, Wrel);

  // QKV projections fused in one launch
  gemm_bf16<<<dim3(8, 32, 3), 256>>>(nullptr, -1);

  attn_mma<<<dim3(16, 16, 4), 128, AT_SMEM>>>();  // -> split ctx

  gemm_bf16<<<dim3(8, 32, 1), 256>>>(out, 3);     // ctx @ Wo -> d_out
}